// round 4
// baseline (speedup 1.0000x reference)
#include <cuda_runtime.h>
#include <math.h>

// Problem constants
#define H   512
#define E   321
#define CC  321
#define T   96
#define P   96
#define B   512
#define G4  2048          // 4*H
#define EP  336           // E padded to mult of 16
#define NCP 384           // CC padded to mult of 64

typedef unsigned long long u64;

// ---------------- scratch (device globals) -----------------------------------
__device__ float g_xTp[(size_t)T * B * EP];    // x_enc transposed+padded (T,B,EP)
__device__ float g_pre[(size_t)T * B * G4];    // batched x@Wih'^T (interleaved)
__device__ float g_ys[(size_t)T * B * H];      // enc layer0 outputs / dec h1 history
__device__ float g_state[6 * B * H];           // h0a,h0b,c0,h1a,h1b,c1
__device__ float g_inp0p[B * EP];              // decoder initial input (padded)

// interleaved weights: row (j*4+g) <- original row (g*H+j)
__device__ float g_eWih0p[G4 * EP];
__device__ float g_eWhh0[G4 * H];
__device__ float g_eWih1[G4 * H];
__device__ float g_eWhh1[G4 * H];
__device__ float g_dWih0p[G4 * EP];
__device__ float g_dWhh0[G4 * H];
__device__ float g_dWih1[G4 * H];
__device__ float g_dWhh1[G4 * H];
__device__ float g_Wfold[G4 * H];              // dWih0 @ fc_W (interleaved rows)
__device__ float g_fcWTp[H * EP];              // fc_W^T padded (H x EP)
__device__ float g_fcWp[NCP * H];              // fc_W padded to NCP rows
__device__ float g_eB0[G4], g_eB1[G4], g_dB0[G4], g_dB0f[G4], g_dB1[G4];
__device__ float g_fcbp[NCP];

// ---------------- f32x2 helpers -------------------------------------------------
__device__ __forceinline__ u64 ffma2(u64 a, u64 b, u64 c) {
    u64 d;
    asm("fma.rn.f32x2 %0, %1, %2, %3;" : "=l"(d) : "l"(a), "l"(b), "l"(c));
    return d;
}
__device__ __forceinline__ u64 dup2(float x) {
    u64 r;
    asm("mov.b64 %0, {%1, %1};" : "=l"(r) : "f"(x));
    return r;
}
__device__ __forceinline__ void unpack2(u64 v, float& lo, float& hi) {
    asm("mov.b64 {%0, %1}, %2;" : "=f"(lo), "=f"(hi) : "l"(v));
}

// ---------------- setup kernels -----------------------------------------------
__global__ void interleave_pad_kernel(const float* __restrict__ src,
                                      float* __restrict__ dst, int K, int Kp)
{
    size_t idx = (size_t)blockIdx.x * blockDim.x + threadIdx.x;
    size_t total = (size_t)G4 * Kp;
    if (idx >= total) return;
    int np = (int)(idx / Kp);
    int k  = (int)(idx % Kp);
    int j = np >> 2, g = np & 3;
    dst[idx] = (k < K) ? src[((size_t)(g * H + j)) * K + k] : 0.f;
}

__global__ void combine_bias_kernel(const float* __restrict__ bih,
                                    const float* __restrict__ bhh,
                                    float* __restrict__ dst)
{
    int n = blockIdx.x * blockDim.x + threadIdx.x;
    if (n >= G4) return;
    int j = n >> 2, g = n & 3;
    dst[n] = bih[g * H + j] + bhh[g * H + j];
}

__global__ void fold_bias_kernel(const float* __restrict__ Wp,
                                 const float* __restrict__ fcb,
                                 const float* __restrict__ dB0,
                                 float* __restrict__ out)
{
    int n = blockIdx.x * blockDim.x + threadIdx.x;
    if (n >= G4) return;
    float s = dB0[n];
    const float* row = Wp + (size_t)n * EP;
    for (int c = 0; c < CC; ++c) s += row[c] * fcb[c];
    out[n] = s;
}

__global__ void fcwt_kernel(const float* __restrict__ fcW, float* __restrict__ dst)
{
    int idx = blockIdx.x * blockDim.x + threadIdx.x;
    if (idx >= H * EP) return;
    int h = idx / EP, c = idx % EP;
    dst[idx] = (c < CC) ? fcW[(size_t)c * H + h] : 0.f;
}

__global__ void fcwpad_kernel(const float* __restrict__ fcW, float* __restrict__ dst)
{
    int idx = blockIdx.x * blockDim.x + threadIdx.x;
    if (idx >= NCP * H) return;
    int n = idx / H, h = idx % H;
    dst[idx] = (n < CC) ? fcW[(size_t)n * H + h] : 0.f;
}

__global__ void fcbpad_kernel(const float* __restrict__ fcb, float* __restrict__ dst)
{
    int n = blockIdx.x * blockDim.x + threadIdx.x;
    if (n >= NCP) return;
    dst[n] = (n < CC) ? fcb[n] : 0.f;
}

__global__ void zero_kernel(float* p, int n)
{
    int i = blockIdx.x * blockDim.x + threadIdx.x;
    if (i < n) p[i] = 0.f;
}

__global__ void transpose_pad_kernel(const float* __restrict__ in, float* __restrict__ out)
{
    size_t idx = (size_t)blockIdx.x * blockDim.x + threadIdx.x;
    size_t total = (size_t)T * B * EP;
    if (idx >= total) return;
    int e = (int)(idx % EP);
    int b = (int)((idx / EP) % B);
    int t = (int)(idx / ((size_t)EP * B));
    out[idx] = (e < E) ? in[(size_t)b * T * E + (size_t)t * E + e] : 0.f;
}

__global__ void copy_last_pad_kernel(const float* __restrict__ x, float* __restrict__ out)
{
    int i = blockIdx.x * blockDim.x + threadIdx.x;
    if (i >= B * EP) return;
    int b = i / EP, e = i % EP;
    out[i] = (e < E) ? x[(size_t)b * T * E + (size_t)(T - 1) * E + e] : 0.f;
}

// ---------------- FFMA2 GEMM (64x64 tile, 128 threads, double-buffered) --------
// Requirements: M%64==0, N%64==0, K%16==0, lda%4==0, ldw%4==0.
// C[m,n] = sum_k A1[m,k]*W1[n,k] (+ A2[m,k]*W2[n,k])
// Per-thread: 8 rows (4 row-pairs, packed f32x2) x 4 cols.
// EPI=0: Cout[m,n] = acc (+bias[n])
// EPI=1: LSTM cell epilogue (interleaved gates; 4 cols/thread = 1 hidden unit)
// EPI=2: batched-fc scatter: row m=(t*B+b) -> out[b*P*CC + t*CC + n], n<Ncheck
__device__ __forceinline__ float sigmf(float x) { return 1.f / (1.f + __expf(-x)); }

template<int EPI>
__global__ __launch_bounds__(128, 4)
void gemm_fast(float* __restrict__ Cout, int ldc,
               const float* __restrict__ A1, int lda1, int K1,
               const float* __restrict__ W1, int ldw1,
               const float* __restrict__ A2, int lda2, int K2,
               const float* __restrict__ W2, int ldw2,
               const float* __restrict__ bias,
               const float* __restrict__ pre,
               float* __restrict__ cst, float* __restrict__ hout,
               float* __restrict__ ysout, int Ncheck)
{
    __shared__ float As[2][16][68];   // [k][m], 16B-aligned rows (68*4=272%16==0)
    __shared__ u64   Ws2[2][16][66];  // [k][n] duplicated pairs (66*8 stride, %16==0)

    const int bm = blockIdx.y * 64;
    const int bn = blockIdx.x * 64;
    const int tid = threadIdx.x;
    const int lrow  = tid & 63;          // loader row within tile
    const int lhalf = (tid >> 6) * 8;    // loader k-offset: 0 or 8
    const int tr = tid >> 4;             // 0..7  -> rows tr*8 .. tr*8+7
    const int tc = tid & 15;             // 0..15 -> cols tc*4 .. tc*4+3

    u64 acc[4][4];
#pragma unroll
    for (int i = 0; i < 4; ++i)
#pragma unroll
        for (int j = 0; j < 4; ++j) acc[i][j] = 0ull;

    for (int phase = 0; phase < 2; ++phase) {
        const float* A = phase ? A2 : A1;
        if (!A) continue;
        const float* W = phase ? W2 : W1;
        const int K   = phase ? K2 : K1;
        const int lda = phase ? lda2 : lda1;
        const int ldw = phase ? ldw2 : ldw1;
        const int nk  = K >> 4;

        const float* Aptr = A + (size_t)(bm + lrow) * lda + lhalf;
        const float* Wptr = W + (size_t)(bn + lrow) * ldw + lhalf;

        __syncthreads();   // smem may still be read from previous phase
        float4 pa0 = *(const float4*)(Aptr);
        float4 pa1 = *(const float4*)(Aptr + 4);
        float4 pw0 = *(const float4*)(Wptr);
        float4 pw1 = *(const float4*)(Wptr + 4);
        {
            As[0][lhalf + 0][lrow] = pa0.x; As[0][lhalf + 1][lrow] = pa0.y;
            As[0][lhalf + 2][lrow] = pa0.z; As[0][lhalf + 3][lrow] = pa0.w;
            As[0][lhalf + 4][lrow] = pa1.x; As[0][lhalf + 5][lrow] = pa1.y;
            As[0][lhalf + 6][lrow] = pa1.z; As[0][lhalf + 7][lrow] = pa1.w;
            Ws2[0][lhalf + 0][lrow] = dup2(pw0.x); Ws2[0][lhalf + 1][lrow] = dup2(pw0.y);
            Ws2[0][lhalf + 2][lrow] = dup2(pw0.z); Ws2[0][lhalf + 3][lrow] = dup2(pw0.w);
            Ws2[0][lhalf + 4][lrow] = dup2(pw1.x); Ws2[0][lhalf + 5][lrow] = dup2(pw1.y);
            Ws2[0][lhalf + 6][lrow] = dup2(pw1.z); Ws2[0][lhalf + 7][lrow] = dup2(pw1.w);
        }
        __syncthreads();

        int buf = 0;
        for (int it = 0; it < nk; ++it) {
            const bool more = (it + 1 < nk);
            if (more) {
                const int ko = (it + 1) * 16;
                pa0 = *(const float4*)(Aptr + ko);
                pa1 = *(const float4*)(Aptr + ko + 4);
                pw0 = *(const float4*)(Wptr + ko);
                pw1 = *(const float4*)(Wptr + ko + 4);
            }
#pragma unroll
            for (int kk = 0; kk < 16; ++kk) {
                const u64* ap = (const u64*)&As[buf][kk][tr * 8];
                const u64* wp = &Ws2[buf][kk][tc * 4];
                u64 a0 = ap[0], a1 = ap[1], a2 = ap[2], a3 = ap[3];
                u64 w0 = wp[0], w1 = wp[1], w2 = wp[2], w3 = wp[3];
                acc[0][0] = ffma2(a0, w0, acc[0][0]);
                acc[0][1] = ffma2(a0, w1, acc[0][1]);
                acc[0][2] = ffma2(a0, w2, acc[0][2]);
                acc[0][3] = ffma2(a0, w3, acc[0][3]);
                acc[1][0] = ffma2(a1, w0, acc[1][0]);
                acc[1][1] = ffma2(a1, w1, acc[1][1]);
                acc[1][2] = ffma2(a1, w2, acc[1][2]);
                acc[1][3] = ffma2(a1, w3, acc[1][3]);
                acc[2][0] = ffma2(a2, w0, acc[2][0]);
                acc[2][1] = ffma2(a2, w1, acc[2][1]);
                acc[2][2] = ffma2(a2, w2, acc[2][2]);
                acc[2][3] = ffma2(a2, w3, acc[2][3]);
                acc[3][0] = ffma2(a3, w0, acc[3][0]);
                acc[3][1] = ffma2(a3, w1, acc[3][1]);
                acc[3][2] = ffma2(a3, w2, acc[3][2]);
                acc[3][3] = ffma2(a3, w3, acc[3][3]);
            }
            if (more) {
                const int nb = buf ^ 1;
                As[nb][lhalf + 0][lrow] = pa0.x; As[nb][lhalf + 1][lrow] = pa0.y;
                As[nb][lhalf + 2][lrow] = pa0.z; As[nb][lhalf + 3][lrow] = pa0.w;
                As[nb][lhalf + 4][lrow] = pa1.x; As[nb][lhalf + 5][lrow] = pa1.y;
                As[nb][lhalf + 6][lrow] = pa1.z; As[nb][lhalf + 7][lrow] = pa1.w;
                Ws2[nb][lhalf + 0][lrow] = dup2(pw0.x); Ws2[nb][lhalf + 1][lrow] = dup2(pw0.y);
                Ws2[nb][lhalf + 2][lrow] = dup2(pw0.z); Ws2[nb][lhalf + 3][lrow] = dup2(pw0.w);
                Ws2[nb][lhalf + 4][lrow] = dup2(pw1.x); Ws2[nb][lhalf + 5][lrow] = dup2(pw1.y);
                Ws2[nb][lhalf + 6][lrow] = dup2(pw1.z); Ws2[nb][lhalf + 7][lrow] = dup2(pw1.w);
                __syncthreads();
                buf = nb;
            }
        }
    }

    // unpack accumulators: rows r = tr*8 + 2p (+1), cols tc*4 + c
    float av[8][4];
#pragma unroll
    for (int p = 0; p < 4; ++p)
#pragma unroll
        for (int c = 0; c < 4; ++c)
            unpack2(acc[p][c], av[2 * p][c], av[2 * p + 1][c]);

    if (EPI == 0) {
        const int gn = bn + tc * 4;
        float4 b4 = make_float4(0.f, 0.f, 0.f, 0.f);
        if (bias) b4 = *(const float4*)&bias[gn];
#pragma unroll
        for (int r = 0; r < 8; ++r) {
            const int gm = bm + tr * 8 + r;
            float4 v;
            v.x = av[r][0] + b4.x; v.y = av[r][1] + b4.y;
            v.z = av[r][2] + b4.z; v.w = av[r][3] + b4.w;
            *(float4*)&Cout[(size_t)gm * ldc + gn] = v;
        }
    } else if (EPI == 1) {
        const int nb4 = bn + tc * 4;       // 4 gate cols of one hidden unit
        const int jh  = (bn >> 2) + tc;    // hidden index
        const float4 b4 = *(const float4*)&bias[nb4];
#pragma unroll
        for (int r = 0; r < 8; ++r) {
            const int gm = bm + tr * 8 + r;
            float gi = av[r][0] + b4.x;
            float gf = av[r][1] + b4.y;
            float gg = av[r][2] + b4.z;
            float go = av[r][3] + b4.w;
            if (pre) {
                const float4 p4 = *(const float4*)&pre[(size_t)gm * G4 + nb4];
                gi += p4.x; gf += p4.y; gg += p4.z; go += p4.w;
            }
            const size_t ci = (size_t)gm * H + jh;
            const float cv = sigmf(gf) * cst[ci] + sigmf(gi) * tanhf(gg);
            const float hv = sigmf(go) * tanhf(cv);
            cst[ci] = cv;
            hout[ci] = hv;
            if (ysout) ysout[ci] = hv;
        }
    } else { // EPI == 2
        const int gn0 = bn + tc * 4;
#pragma unroll
        for (int r = 0; r < 8; ++r) {
            const int gm = bm + tr * 8 + r;
            const int bb = gm & (B - 1);
            const int tt = gm >> 9;        // B = 512
            float* o = Cout + (size_t)bb * (P * CC) + (size_t)tt * CC;
#pragma unroll
            for (int c = 0; c < 4; ++c) {
                const int gn = gn0 + c;
                if (gn < Ncheck) o[gn] = av[r][c] + bias[gn];
            }
        }
    }
}

// ---------------- launch helpers -----------------------------------------------
static inline void launch_lstm(const float* A1, int lda1, int K1, const float* W1, int ldw1,
                               const float* A2, int lda2, int K2, const float* W2, int ldw2,
                               const float* bias, const float* pre,
                               float* cst, float* hout, float* ysout)
{
    dim3 grid(G4 / 64, B / 64);
    gemm_fast<1><<<grid, 128>>>(nullptr, 0, A1, lda1, K1, W1, ldw1,
                                A2, lda2, K2, W2, ldw2,
                                bias, pre, cst, hout, ysout, 0);
}

static inline void launch_plain(float* Cp, int ldc,
                                const float* A, int lda, int K,
                                const float* W, int ldw,
                                const float* bias, int M, int N)
{
    dim3 grid(N / 64, M / 64);
    gemm_fast<0><<<grid, 128>>>(Cp, ldc, A, lda, K, W, ldw,
                                nullptr, 0, 0, nullptr, 0,
                                bias, nullptr, nullptr, nullptr, nullptr, 0);
}

// ---------------- entry ----------------------------------------------------------
extern "C" void kernel_launch(void* const* d_in, const int* in_sizes, int n_in,
                              void* d_out, int out_size)
{
    const float* x_enc  = (const float*)d_in[0];
    const float* e_Wih0 = (const float*)d_in[4];
    const float* e_Whh0 = (const float*)d_in[5];
    const float* e_bih0 = (const float*)d_in[6];
    const float* e_bhh0 = (const float*)d_in[7];
    const float* e_Wih1 = (const float*)d_in[8];
    const float* e_Whh1 = (const float*)d_in[9];
    const float* e_bih1 = (const float*)d_in[10];
    const float* e_bhh1 = (const float*)d_in[11];
    const float* d_Wih0 = (const float*)d_in[12];
    const float* d_Whh0 = (const float*)d_in[13];
    const float* d_bih0 = (const float*)d_in[14];
    const float* d_bhh0 = (const float*)d_in[15];
    const float* d_Wih1 = (const float*)d_in[16];
    const float* d_Whh1 = (const float*)d_in[17];
    const float* d_bih1 = (const float*)d_in[18];
    const float* d_bhh1 = (const float*)d_in[19];
    const float* fc_W   = (const float*)d_in[20];
    const float* fc_b   = (const float*)d_in[21];
    float* out = (float*)d_out;

    float *xTp, *pre, *ys, *st, *inp0p;
    float *eWih0p, *eWhh0, *eWih1, *eWhh1, *dWih0p, *dWhh0, *dWih1, *dWhh1;
    float *Wfold, *fcWTp, *fcWp, *eB0, *eB1, *dB0, *dB0f, *dB1, *fcbp;
    cudaGetSymbolAddress((void**)&xTp,    g_xTp);
    cudaGetSymbolAddress((void**)&pre,    g_pre);
    cudaGetSymbolAddress((void**)&ys,     g_ys);
    cudaGetSymbolAddress((void**)&st,     g_state);
    cudaGetSymbolAddress((void**)&inp0p,  g_inp0p);
    cudaGetSymbolAddress((void**)&eWih0p, g_eWih0p);
    cudaGetSymbolAddress((void**)&eWhh0,  g_eWhh0);
    cudaGetSymbolAddress((void**)&eWih1,  g_eWih1);
    cudaGetSymbolAddress((void**)&eWhh1,  g_eWhh1);
    cudaGetSymbolAddress((void**)&dWih0p, g_dWih0p);
    cudaGetSymbolAddress((void**)&dWhh0,  g_dWhh0);
    cudaGetSymbolAddress((void**)&dWih1,  g_dWih1);
    cudaGetSymbolAddress((void**)&dWhh1,  g_dWhh1);
    cudaGetSymbolAddress((void**)&Wfold,  g_Wfold);
    cudaGetSymbolAddress((void**)&fcWTp,  g_fcWTp);
    cudaGetSymbolAddress((void**)&fcWp,   g_fcWp);
    cudaGetSymbolAddress((void**)&eB0,    g_eB0);
    cudaGetSymbolAddress((void**)&eB1,    g_eB1);
    cudaGetSymbolAddress((void**)&dB0,    g_dB0);
    cudaGetSymbolAddress((void**)&dB0f,   g_dB0f);
    cudaGetSymbolAddress((void**)&dB1,    g_dB1);
    cudaGetSymbolAddress((void**)&fcbp,   g_fcbp);

    const size_t BH = (size_t)B * H;
    float* h0buf[2] = { st,          st + BH };
    float* c0      =   st + 2 * BH;
    float* h1buf[2] = { st + 3 * BH, st + 4 * BH };
    float* c1st    =   st + 5 * BH;

    const int thr = 256;

    // ---- setup: weight interleave (+pad), bias combine, fc pads, fold ----
    {
        size_t nEp = (size_t)G4 * EP, nH = (size_t)G4 * H;
        interleave_pad_kernel<<<(unsigned)((nEp + thr - 1) / thr), thr>>>(e_Wih0, eWih0p, E, EP);
        interleave_pad_kernel<<<(unsigned)((nH + thr - 1) / thr), thr>>>(e_Whh0, eWhh0, H, H);
        interleave_pad_kernel<<<(unsigned)((nH + thr - 1) / thr), thr>>>(e_Wih1, eWih1, H, H);
        interleave_pad_kernel<<<(unsigned)((nH + thr - 1) / thr), thr>>>(e_Whh1, eWhh1, H, H);
        interleave_pad_kernel<<<(unsigned)((nEp + thr - 1) / thr), thr>>>(d_Wih0, dWih0p, E, EP);
        interleave_pad_kernel<<<(unsigned)((nH + thr - 1) / thr), thr>>>(d_Whh0, dWhh0, H, H);
        interleave_pad_kernel<<<(unsigned)((nH + thr - 1) / thr), thr>>>(d_Wih1, dWih1, H, H);
        interleave_pad_kernel<<<(unsigned)((nH + thr - 1) / thr), thr>>>(d_Whh1, dWhh1, H, H);
        combine_bias_kernel<<<(G4 + thr - 1) / thr, thr>>>(e_bih0, e_bhh0, eB0);
        combine_bias_kernel<<<(G4 + thr - 1) / thr, thr>>>(e_bih1, e_bhh1, eB1);
        combine_bias_kernel<<<(G4 + thr - 1) / thr, thr>>>(d_bih0, d_bhh0, dB0);
        combine_bias_kernel<<<(G4 + thr - 1) / thr, thr>>>(d_bih1, d_bhh1, dB1);
        fcwt_kernel<<<(H * EP + thr - 1) / thr, thr>>>(fc_W, fcWTp);
        fcwpad_kernel<<<(NCP * H + thr - 1) / thr, thr>>>(fc_W, fcWp);
        fcbpad_kernel<<<(NCP + thr - 1) / thr, thr>>>(fc_b, fcbp);
        // Wfold = dWih0p @ fcWTp^T : (G4 x H), K=EP
        launch_plain(Wfold, H, dWih0p, EP, EP, fcWTp, EP, nullptr, G4, H);
        fold_bias_kernel<<<(G4 + thr - 1) / thr, thr>>>(dWih0p, fc_b, dB0, dB0f);
    }

    // ---- zero states ----
    zero_kernel<<<(6 * B * H + thr - 1) / thr, thr>>>(st, 6 * B * H);

    // ---- transpose+pad x_enc ----
    {
        size_t total = (size_t)T * B * EP;
        transpose_pad_kernel<<<(unsigned)((total + thr - 1) / thr), thr>>>(x_enc, xTp);
    }

    // ---- encoder layer0 batched input GEMM ----
    launch_plain(pre, G4, xTp, EP, EP, eWih0p, EP, nullptr, T * B, G4);

    // ---- encoder layer0 recurrence ----
    int ch0 = 0;
    for (int t = 0; t < T; ++t) {
        launch_lstm(h0buf[ch0], H, H, eWhh0, H, nullptr, 0, 0, nullptr, 0,
                    eB0, pre + (size_t)t * B * G4, c0, h0buf[ch0 ^ 1],
                    ys + (size_t)t * BH);
        ch0 ^= 1;
    }

    // ---- encoder layer1 batched input GEMM ----
    launch_plain(pre, G4, ys, H, H, eWih1, H, nullptr, T * B, G4);

    // ---- encoder layer1 recurrence ----
    int ch1 = 0;
    for (int t = 0; t < T; ++t) {
        launch_lstm(h1buf[ch1], H, H, eWhh1, H, nullptr, 0, 0, nullptr, 0,
                    eB1, pre + (size_t)t * B * G4, c1st, h1buf[ch1 ^ 1], nullptr);
        ch1 ^= 1;
    }

    // ---- decoder initial input ----
    copy_last_pad_kernel<<<(B * EP + thr - 1) / thr, thr>>>(x_enc, inp0p);

    // ---- decoder recurrence (fc folded into cell0; h1 history -> g_ys) ----
    for (int t = 0; t < P; ++t) {
        if (t == 0) {
            launch_lstm(inp0p, EP, EP, dWih0p, EP,
                        h0buf[ch0], H, H, dWhh0, H,
                        dB0, nullptr, c0, h0buf[ch0 ^ 1], nullptr);
        } else {
            launch_lstm(h1buf[ch1], H, H, Wfold, H,
                        h0buf[ch0], H, H, dWhh0, H,
                        dB0f, nullptr, c0, h0buf[ch0 ^ 1], nullptr);
        }
        ch0 ^= 1;

        launch_lstm(h0buf[ch0], H, H, dWih1, H,
                    h1buf[ch1], H, H, dWhh1, H,
                    dB1, nullptr, c1st, h1buf[ch1 ^ 1],
                    ys + (size_t)t * BH);
        ch1 ^= 1;
    }

    // ---- batched final fc: out[b,t,:] = h1_hist[t,b,:] @ fc_W^T + fc_b ----
    {
        dim3 grid(NCP / 64, (T * B) / 64);
        gemm_fast<2><<<grid, 128>>>(out, 0, ys, H, H, fcWp, H,
                                    nullptr, 0, 0, nullptr, 0,
                                    fcbp, nullptr, nullptr, nullptr, nullptr, CC);
    }
}

// round 5
// speedup vs baseline: 1.0017x; 1.0017x over previous
#include <cuda_runtime.h>
#include <math.h>

// Problem constants
#define H   512
#define E   321
#define CC  321
#define T   96
#define P   96
#define B   512
#define G4  2048          // 4*H
#define EP  336           // E padded to mult of 16
#define NCP 384           // CC padded to mult of 64

typedef unsigned long long u64;

// ---------------- scratch (device globals) -----------------------------------
__device__ float g_xTp[(size_t)T * B * EP];    // x_enc transposed+padded (T,B,EP)
__device__ float g_pre[(size_t)T * B * G4];    // batched x@Wih'^T (interleaved)
__device__ float g_ys[(size_t)T * B * H];      // enc layer0 outputs / dec h1 history
__device__ float g_state[6 * B * H];           // h0a,h0b,c0,h1a,h1b,c1
__device__ float g_inp0p[B * EP];              // decoder initial input (padded)

// interleaved weights: row (j*4+g) <- original row (g*H+j)
__device__ float g_eWih0p[G4 * EP];
__device__ float g_eWhh0[G4 * H];
__device__ float g_eWih1[G4 * H];
__device__ float g_eWhh1[G4 * H];
__device__ float g_dWih0p[G4 * EP];
__device__ float g_dWhh0[G4 * H];
__device__ float g_dWih1[G4 * H];
__device__ float g_dWhh1[G4 * H];
__device__ float g_Wfold[G4 * H];              // dWih0 @ fc_W (interleaved rows)
__device__ float g_fcWTp[H * EP];              // fc_W^T padded (H x EP)
__device__ float g_fcWp[NCP * H];              // fc_W padded to NCP rows
__device__ float g_eB0[G4], g_eB1[G4], g_dB0[G4], g_dB0f[G4], g_dB1[G4];
__device__ float g_fcbp[NCP];

// ---------------- f32x2 helpers -------------------------------------------------
__device__ __forceinline__ u64 ffma2(u64 a, u64 b, u64 c) {
    u64 d;
    asm("fma.rn.f32x2 %0, %1, %2, %3;" : "=l"(d) : "l"(a), "l"(b), "l"(c));
    return d;
}
__device__ __forceinline__ u64 dup2(float x) {
    u64 r;
    asm("mov.b64 %0, {%1, %1};" : "=l"(r) : "f"(x));
    return r;
}
__device__ __forceinline__ void unpack2(u64 v, float& lo, float& hi) {
    asm("mov.b64 {%0, %1}, %2;" : "=f"(lo), "=f"(hi) : "l"(v));
}

// ---------------- setup kernels -----------------------------------------------
__global__ void interleave_pad_kernel(const float* __restrict__ src,
                                      float* __restrict__ dst, int K, int Kp)
{
    size_t idx = (size_t)blockIdx.x * blockDim.x + threadIdx.x;
    size_t total = (size_t)G4 * Kp;
    if (idx >= total) return;
    int np = (int)(idx / Kp);
    int k  = (int)(idx % Kp);
    int j = np >> 2, g = np & 3;
    dst[idx] = (k < K) ? src[((size_t)(g * H + j)) * K + k] : 0.f;
}

__global__ void combine_bias_kernel(const float* __restrict__ bih,
                                    const float* __restrict__ bhh,
                                    float* __restrict__ dst)
{
    int n = blockIdx.x * blockDim.x + threadIdx.x;
    if (n >= G4) return;
    int j = n >> 2, g = n & 3;
    dst[n] = bih[g * H + j] + bhh[g * H + j];
}

__global__ void fold_bias_kernel(const float* __restrict__ Wp,
                                 const float* __restrict__ fcb,
                                 const float* __restrict__ dB0,
                                 float* __restrict__ out)
{
    int n = blockIdx.x * blockDim.x + threadIdx.x;
    if (n >= G4) return;
    float s = dB0[n];
    const float* row = Wp + (size_t)n * EP;
    for (int c = 0; c < CC; ++c) s += row[c] * fcb[c];
    out[n] = s;
}

__global__ void fcwt_kernel(const float* __restrict__ fcW, float* __restrict__ dst)
{
    int idx = blockIdx.x * blockDim.x + threadIdx.x;
    if (idx >= H * EP) return;
    int h = idx / EP, c = idx % EP;
    dst[idx] = (c < CC) ? fcW[(size_t)c * H + h] : 0.f;
}

__global__ void fcwpad_kernel(const float* __restrict__ fcW, float* __restrict__ dst)
{
    int idx = blockIdx.x * blockDim.x + threadIdx.x;
    if (idx >= NCP * H) return;
    int n = idx / H, h = idx % H;
    dst[idx] = (n < CC) ? fcW[(size_t)n * H + h] : 0.f;
}

__global__ void fcbpad_kernel(const float* __restrict__ fcb, float* __restrict__ dst)
{
    int n = blockIdx.x * blockDim.x + threadIdx.x;
    if (n >= NCP) return;
    dst[n] = (n < CC) ? fcb[n] : 0.f;
}

__global__ void zero_kernel(float* p, int n)
{
    int i = blockIdx.x * blockDim.x + threadIdx.x;
    if (i < n) p[i] = 0.f;
}

__global__ void transpose_pad_kernel(const float* __restrict__ in, float* __restrict__ out)
{
    size_t idx = (size_t)blockIdx.x * blockDim.x + threadIdx.x;
    size_t total = (size_t)T * B * EP;
    if (idx >= total) return;
    int e = (int)(idx % EP);
    int b = (int)((idx / EP) % B);
    int t = (int)(idx / ((size_t)EP * B));
    out[idx] = (e < E) ? in[(size_t)b * T * E + (size_t)t * E + e] : 0.f;
}

__global__ void copy_last_pad_kernel(const float* __restrict__ x, float* __restrict__ out)
{
    int i = blockIdx.x * blockDim.x + threadIdx.x;
    if (i >= B * EP) return;
    int b = i / EP, e = i % EP;
    out[i] = (e < E) ? x[(size_t)b * T * E + (size_t)(T - 1) * E + e] : 0.f;
}

// ---------------- FFMA2 GEMM (64x64 tile, 128 threads, double-buffered) --------
// Requirements: M%64==0, N%64==0, K%16==0, lda%4==0, ldw%4==0.
// C[m,n] = sum_k A1[m,k]*W1[n,k] (+ A2[m,k]*W2[n,k])
// Per-thread: 8 rows (4 row-pairs, packed f32x2) x 4 cols.
// EPI=0: Cout[m,n] = acc (+bias[n])
// EPI=1: LSTM cell epilogue (interleaved gates; 4 cols/thread = 1 hidden unit)
// EPI=2: batched-fc scatter: row m=(t*B+b) -> out[b*P*CC + t*CC + n], n<Ncheck
__device__ __forceinline__ float sigmf(float x) { return 1.f / (1.f + __expf(-x)); }

template<int EPI>
__global__ __launch_bounds__(128, 4)
void gemm_fast(float* __restrict__ Cout, int ldc,
               const float* __restrict__ A1, int lda1, int K1,
               const float* __restrict__ W1, int ldw1,
               const float* __restrict__ A2, int lda2, int K2,
               const float* __restrict__ W2, int ldw2,
               const float* __restrict__ bias,
               const float* __restrict__ pre,
               float* __restrict__ cst, float* __restrict__ hout,
               float* __restrict__ ysout, int Ncheck)
{
    __shared__ float As[2][16][68];   // [k][m], 16B-aligned rows (68*4=272%16==0)
    __shared__ u64   Ws2[2][16][66];  // [k][n] duplicated pairs (66*8 stride, %16==0)

    const int bm = blockIdx.y * 64;
    const int bn = blockIdx.x * 64;
    const int tid = threadIdx.x;
    const int lrow  = tid & 63;          // loader row within tile
    const int lhalf = (tid >> 6) * 8;    // loader k-offset: 0 or 8
    const int tr = tid >> 4;             // 0..7  -> rows tr*8 .. tr*8+7
    const int tc = tid & 15;             // 0..15 -> cols tc*4 .. tc*4+3

    u64 acc[4][4];
#pragma unroll
    for (int i = 0; i < 4; ++i)
#pragma unroll
        for (int j = 0; j < 4; ++j) acc[i][j] = 0ull;

    for (int phase = 0; phase < 2; ++phase) {
        const float* A = phase ? A2 : A1;
        if (!A) continue;
        const float* W = phase ? W2 : W1;
        const int K   = phase ? K2 : K1;
        const int lda = phase ? lda2 : lda1;
        const int ldw = phase ? ldw2 : ldw1;
        const int nk  = K >> 4;

        const float* Aptr = A + (size_t)(bm + lrow) * lda + lhalf;
        const float* Wptr = W + (size_t)(bn + lrow) * ldw + lhalf;

        __syncthreads();   // smem may still be read from previous phase
        float4 pa0 = *(const float4*)(Aptr);
        float4 pa1 = *(const float4*)(Aptr + 4);
        float4 pw0 = *(const float4*)(Wptr);
        float4 pw1 = *(const float4*)(Wptr + 4);
        {
            As[0][lhalf + 0][lrow] = pa0.x; As[0][lhalf + 1][lrow] = pa0.y;
            As[0][lhalf + 2][lrow] = pa0.z; As[0][lhalf + 3][lrow] = pa0.w;
            As[0][lhalf + 4][lrow] = pa1.x; As[0][lhalf + 5][lrow] = pa1.y;
            As[0][lhalf + 6][lrow] = pa1.z; As[0][lhalf + 7][lrow] = pa1.w;
            Ws2[0][lhalf + 0][lrow] = dup2(pw0.x); Ws2[0][lhalf + 1][lrow] = dup2(pw0.y);
            Ws2[0][lhalf + 2][lrow] = dup2(pw0.z); Ws2[0][lhalf + 3][lrow] = dup2(pw0.w);
            Ws2[0][lhalf + 4][lrow] = dup2(pw1.x); Ws2[0][lhalf + 5][lrow] = dup2(pw1.y);
            Ws2[0][lhalf + 6][lrow] = dup2(pw1.z); Ws2[0][lhalf + 7][lrow] = dup2(pw1.w);
        }
        __syncthreads();

        int buf = 0;
        for (int it = 0; it < nk; ++it) {
            const bool more = (it + 1 < nk);
            if (more) {
                const int ko = (it + 1) * 16;
                pa0 = *(const float4*)(Aptr + ko);
                pa1 = *(const float4*)(Aptr + ko + 4);
                pw0 = *(const float4*)(Wptr + ko);
                pw1 = *(const float4*)(Wptr + ko + 4);
            }
#pragma unroll
            for (int kk = 0; kk < 16; ++kk) {
                const u64* ap = (const u64*)&As[buf][kk][tr * 8];
                const u64* wp = &Ws2[buf][kk][tc * 4];
                u64 a0 = ap[0], a1 = ap[1], a2 = ap[2], a3 = ap[3];
                u64 w0 = wp[0], w1 = wp[1], w2 = wp[2], w3 = wp[3];
                acc[0][0] = ffma2(a0, w0, acc[0][0]);
                acc[0][1] = ffma2(a0, w1, acc[0][1]);
                acc[0][2] = ffma2(a0, w2, acc[0][2]);
                acc[0][3] = ffma2(a0, w3, acc[0][3]);
                acc[1][0] = ffma2(a1, w0, acc[1][0]);
                acc[1][1] = ffma2(a1, w1, acc[1][1]);
                acc[1][2] = ffma2(a1, w2, acc[1][2]);
                acc[1][3] = ffma2(a1, w3, acc[1][3]);
                acc[2][0] = ffma2(a2, w0, acc[2][0]);
                acc[2][1] = ffma2(a2, w1, acc[2][1]);
                acc[2][2] = ffma2(a2, w2, acc[2][2]);
                acc[2][3] = ffma2(a2, w3, acc[2][3]);
                acc[3][0] = ffma2(a3, w0, acc[3][0]);
                acc[3][1] = ffma2(a3, w1, acc[3][1]);
                acc[3][2] = ffma2(a3, w2, acc[3][2]);
                acc[3][3] = ffma2(a3, w3, acc[3][3]);
            }
            if (more) {
                const int nb = buf ^ 1;
                As[nb][lhalf + 0][lrow] = pa0.x; As[nb][lhalf + 1][lrow] = pa0.y;
                As[nb][lhalf + 2][lrow] = pa0.z; As[nb][lhalf + 3][lrow] = pa0.w;
                As[nb][lhalf + 4][lrow] = pa1.x; As[nb][lhalf + 5][lrow] = pa1.y;
                As[nb][lhalf + 6][lrow] = pa1.z; As[nb][lhalf + 7][lrow] = pa1.w;
                Ws2[nb][lhalf + 0][lrow] = dup2(pw0.x); Ws2[nb][lhalf + 1][lrow] = dup2(pw0.y);
                Ws2[nb][lhalf + 2][lrow] = dup2(pw0.z); Ws2[nb][lhalf + 3][lrow] = dup2(pw0.w);
                Ws2[nb][lhalf + 4][lrow] = dup2(pw1.x); Ws2[nb][lhalf + 5][lrow] = dup2(pw1.y);
                Ws2[nb][lhalf + 6][lrow] = dup2(pw1.z); Ws2[nb][lhalf + 7][lrow] = dup2(pw1.w);
                __syncthreads();
                buf = nb;
            }
        }
    }

    // unpack accumulators: rows r = tr*8 + 2p (+1), cols tc*4 + c
    float av[8][4];
#pragma unroll
    for (int p = 0; p < 4; ++p)
#pragma unroll
        for (int c = 0; c < 4; ++c)
            unpack2(acc[p][c], av[2 * p][c], av[2 * p + 1][c]);

    if (EPI == 0) {
        const int gn = bn + tc * 4;
        float4 b4 = make_float4(0.f, 0.f, 0.f, 0.f);
        if (bias) b4 = *(const float4*)&bias[gn];
#pragma unroll
        for (int r = 0; r < 8; ++r) {
            const int gm = bm + tr * 8 + r;
            float4 v;
            v.x = av[r][0] + b4.x; v.y = av[r][1] + b4.y;
            v.z = av[r][2] + b4.z; v.w = av[r][3] + b4.w;
            *(float4*)&Cout[(size_t)gm * ldc + gn] = v;
        }
    } else if (EPI == 1) {
        const int nb4 = bn + tc * 4;       // 4 gate cols of one hidden unit
        const int jh  = (bn >> 2) + tc;    // hidden index
        const float4 b4 = *(const float4*)&bias[nb4];
#pragma unroll
        for (int r = 0; r < 8; ++r) {
            const int gm = bm + tr * 8 + r;
            float gi = av[r][0] + b4.x;
            float gf = av[r][1] + b4.y;
            float gg = av[r][2] + b4.z;
            float go = av[r][3] + b4.w;
            if (pre) {
                const float4 p4 = *(const float4*)&pre[(size_t)gm * G4 + nb4];
                gi += p4.x; gf += p4.y; gg += p4.z; go += p4.w;
            }
            const size_t ci = (size_t)gm * H + jh;
            const float cv = sigmf(gf) * cst[ci] + sigmf(gi) * tanhf(gg);
            const float hv = sigmf(go) * tanhf(cv);
            cst[ci] = cv;
            hout[ci] = hv;
            if (ysout) ysout[ci] = hv;
        }
    } else { // EPI == 2
        const int gn0 = bn + tc * 4;
#pragma unroll
        for (int r = 0; r < 8; ++r) {
            const int gm = bm + tr * 8 + r;
            const int bb = gm & (B - 1);
            const int tt = gm >> 9;        // B = 512
            float* o = Cout + (size_t)bb * (P * CC) + (size_t)tt * CC;
#pragma unroll
            for (int c = 0; c < 4; ++c) {
                const int gn = gn0 + c;
                if (gn < Ncheck) o[gn] = av[r][c] + bias[gn];
            }
        }
    }
}

// ---------------- launch helpers -----------------------------------------------
static inline void launch_lstm(const float* A1, int lda1, int K1, const float* W1, int ldw1,
                               const float* A2, int lda2, int K2, const float* W2, int ldw2,
                               const float* bias, const float* pre,
                               float* cst, float* hout, float* ysout)
{
    dim3 grid(G4 / 64, B / 64);
    gemm_fast<1><<<grid, 128>>>(nullptr, 0, A1, lda1, K1, W1, ldw1,
                                A2, lda2, K2, W2, ldw2,
                                bias, pre, cst, hout, ysout, 0);
}

static inline void launch_plain(float* Cp, int ldc,
                                const float* A, int lda, int K,
                                const float* W, int ldw,
                                const float* bias, int M, int N)
{
    dim3 grid(N / 64, M / 64);
    gemm_fast<0><<<grid, 128>>>(Cp, ldc, A, lda, K, W, ldw,
                                nullptr, 0, 0, nullptr, 0,
                                bias, nullptr, nullptr, nullptr, nullptr, 0);
}

// ---------------- entry ----------------------------------------------------------
extern "C" void kernel_launch(void* const* d_in, const int* in_sizes, int n_in,
                              void* d_out, int out_size)
{
    const float* x_enc  = (const float*)d_in[0];
    const float* e_Wih0 = (const float*)d_in[4];
    const float* e_Whh0 = (const float*)d_in[5];
    const float* e_bih0 = (const float*)d_in[6];
    const float* e_bhh0 = (const float*)d_in[7];
    const float* e_Wih1 = (const float*)d_in[8];
    const float* e_Whh1 = (const float*)d_in[9];
    const float* e_bih1 = (const float*)d_in[10];
    const float* e_bhh1 = (const float*)d_in[11];
    const float* d_Wih0 = (const float*)d_in[12];
    const float* d_Whh0 = (const float*)d_in[13];
    const float* d_bih0 = (const float*)d_in[14];
    const float* d_bhh0 = (const float*)d_in[15];
    const float* d_Wih1 = (const float*)d_in[16];
    const float* d_Whh1 = (const float*)d_in[17];
    const float* d_bih1 = (const float*)d_in[18];
    const float* d_bhh1 = (const float*)d_in[19];
    const float* fc_W   = (const float*)d_in[20];
    const float* fc_b   = (const float*)d_in[21];
    float* out = (float*)d_out;

    float *xTp, *pre, *ys, *st, *inp0p;
    float *eWih0p, *eWhh0, *eWih1, *eWhh1, *dWih0p, *dWhh0, *dWih1, *dWhh1;
    float *Wfold, *fcWTp, *fcWp, *eB0, *eB1, *dB0, *dB0f, *dB1, *fcbp;
    cudaGetSymbolAddress((void**)&xTp,    g_xTp);
    cudaGetSymbolAddress((void**)&pre,    g_pre);
    cudaGetSymbolAddress((void**)&ys,     g_ys);
    cudaGetSymbolAddress((void**)&st,     g_state);
    cudaGetSymbolAddress((void**)&inp0p,  g_inp0p);
    cudaGetSymbolAddress((void**)&eWih0p, g_eWih0p);
    cudaGetSymbolAddress((void**)&eWhh0,  g_eWhh0);
    cudaGetSymbolAddress((void**)&eWih1,  g_eWih1);
    cudaGetSymbolAddress((void**)&eWhh1,  g_eWhh1);
    cudaGetSymbolAddress((void**)&dWih0p, g_dWih0p);
    cudaGetSymbolAddress((void**)&dWhh0,  g_dWhh0);
    cudaGetSymbolAddress((void**)&dWih1,  g_dWih1);
    cudaGetSymbolAddress((void**)&dWhh1,  g_dWhh1);
    cudaGetSymbolAddress((void**)&Wfold,  g_Wfold);
    cudaGetSymbolAddress((void**)&fcWTp,  g_fcWTp);
    cudaGetSymbolAddress((void**)&fcWp,   g_fcWp);
    cudaGetSymbolAddress((void**)&eB0,    g_eB0);
    cudaGetSymbolAddress((void**)&eB1,    g_eB1);
    cudaGetSymbolAddress((void**)&dB0,    g_dB0);
    cudaGetSymbolAddress((void**)&dB0f,   g_dB0f);
    cudaGetSymbolAddress((void**)&dB1,    g_dB1);
    cudaGetSymbolAddress((void**)&fcbp,   g_fcbp);

    const size_t BH = (size_t)B * H;
    float* h0buf[2] = { st,          st + BH };
    float* c0      =   st + 2 * BH;
    float* h1buf[2] = { st + 3 * BH, st + 4 * BH };
    float* c1st    =   st + 5 * BH;

    const int thr = 256;

    // ---- setup: weight interleave (+pad), bias combine, fc pads, fold ----
    {
        size_t nEp = (size_t)G4 * EP, nH = (size_t)G4 * H;
        interleave_pad_kernel<<<(unsigned)((nEp + thr - 1) / thr), thr>>>(e_Wih0, eWih0p, E, EP);
        interleave_pad_kernel<<<(unsigned)((nH + thr - 1) / thr), thr>>>(e_Whh0, eWhh0, H, H);
        interleave_pad_kernel<<<(unsigned)((nH + thr - 1) / thr), thr>>>(e_Wih1, eWih1, H, H);
        interleave_pad_kernel<<<(unsigned)((nH + thr - 1) / thr), thr>>>(e_Whh1, eWhh1, H, H);
        interleave_pad_kernel<<<(unsigned)((nEp + thr - 1) / thr), thr>>>(d_Wih0, dWih0p, E, EP);
        interleave_pad_kernel<<<(unsigned)((nH + thr - 1) / thr), thr>>>(d_Whh0, dWhh0, H, H);
        interleave_pad_kernel<<<(unsigned)((nH + thr - 1) / thr), thr>>>(d_Wih1, dWih1, H, H);
        interleave_pad_kernel<<<(unsigned)((nH + thr - 1) / thr), thr>>>(d_Whh1, dWhh1, H, H);
        combine_bias_kernel<<<(G4 + thr - 1) / thr, thr>>>(e_bih0, e_bhh0, eB0);
        combine_bias_kernel<<<(G4 + thr - 1) / thr, thr>>>(e_bih1, e_bhh1, eB1);
        combine_bias_kernel<<<(G4 + thr - 1) / thr, thr>>>(d_bih0, d_bhh0, dB0);
        combine_bias_kernel<<<(G4 + thr - 1) / thr, thr>>>(d_bih1, d_bhh1, dB1);
        fcwt_kernel<<<(H * EP + thr - 1) / thr, thr>>>(fc_W, fcWTp);
        fcwpad_kernel<<<(NCP * H + thr - 1) / thr, thr>>>(fc_W, fcWp);
        fcbpad_kernel<<<(NCP + thr - 1) / thr, thr>>>(fc_b, fcbp);
        // Wfold = dWih0p @ fcWTp^T : (G4 x H), K=EP
        launch_plain(Wfold, H, dWih0p, EP, EP, fcWTp, EP, nullptr, G4, H);
        fold_bias_kernel<<<(G4 + thr - 1) / thr, thr>>>(dWih0p, fc_b, dB0, dB0f);
    }

    // ---- zero states ----
    zero_kernel<<<(6 * B * H + thr - 1) / thr, thr>>>(st, 6 * B * H);

    // ---- transpose+pad x_enc ----
    {
        size_t total = (size_t)T * B * EP;
        transpose_pad_kernel<<<(unsigned)((total + thr - 1) / thr), thr>>>(x_enc, xTp);
    }

    // ---- encoder layer0 batched input GEMM ----
    launch_plain(pre, G4, xTp, EP, EP, eWih0p, EP, nullptr, T * B, G4);

    // ---- encoder layer0 recurrence ----
    int ch0 = 0;
    for (int t = 0; t < T; ++t) {
        launch_lstm(h0buf[ch0], H, H, eWhh0, H, nullptr, 0, 0, nullptr, 0,
                    eB0, pre + (size_t)t * B * G4, c0, h0buf[ch0 ^ 1],
                    ys + (size_t)t * BH);
        ch0 ^= 1;
    }

    // ---- encoder layer1 batched input GEMM ----
    launch_plain(pre, G4, ys, H, H, eWih1, H, nullptr, T * B, G4);

    // ---- encoder layer1 recurrence ----
    int ch1 = 0;
    for (int t = 0; t < T; ++t) {
        launch_lstm(h1buf[ch1], H, H, eWhh1, H, nullptr, 0, 0, nullptr, 0,
                    eB1, pre + (size_t)t * B * G4, c1st, h1buf[ch1 ^ 1], nullptr);
        ch1 ^= 1;
    }

    // ---- decoder initial input ----
    copy_last_pad_kernel<<<(B * EP + thr - 1) / thr, thr>>>(x_enc, inp0p);

    // ---- decoder recurrence (fc folded into cell0; h1 history -> g_ys) ----
    for (int t = 0; t < P; ++t) {
        if (t == 0) {
            launch_lstm(inp0p, EP, EP, dWih0p, EP,
                        h0buf[ch0], H, H, dWhh0, H,
                        dB0, nullptr, c0, h0buf[ch0 ^ 1], nullptr);
        } else {
            launch_lstm(h1buf[ch1], H, H, Wfold, H,
                        h0buf[ch0], H, H, dWhh0, H,
                        dB0f, nullptr, c0, h0buf[ch0 ^ 1], nullptr);
        }
        ch0 ^= 1;

        launch_lstm(h0buf[ch0], H, H, dWih1, H,
                    h1buf[ch1], H, H, dWhh1, H,
                    dB1, nullptr, c1st, h1buf[ch1 ^ 1],
                    ys + (size_t)t * BH);
        ch1 ^= 1;
    }

    // ---- batched final fc: out[b,t,:] = h1_hist[t,b,:] @ fc_W^T + fc_b ----
    {
        dim3 grid(NCP / 64, (T * B) / 64);
        gemm_fast<2><<<grid, 128>>>(out, 0, ys, H, H, fcWp, H,
                                    nullptr, 0, 0, nullptr, 0,
                                    fcbp, nullptr, nullptr, nullptr, nullptr, CC);
    }
}

// round 7
// speedup vs baseline: 2.0194x; 2.0160x over previous
#include <cuda_runtime.h>
#include <cuda_bf16.h>
#include <math.h>

#define H   512
#define E   321
#define CCn 321
#define Tn  96
#define Pn  96
#define Bn  512
#define G4  2048
#define EPB 384            // E padded
#define NCP 384            // CC padded
#define TB  (Tn*Bn)
#define K3E (3*EPB)        // 1152
#define K3H (3*H)          // 1536

typedef __nv_bfloat16 bf16;
typedef unsigned int u32;

// ---------------- device globals ------------------------------------------------
__device__ bf16  g_eWih0[(size_t)G4*K3E];   // W-style [hi|lo|hi]
__device__ bf16  g_dWih0[(size_t)G4*K3E];
__device__ bf16  g_eWhh0[(size_t)G4*K3H];
__device__ bf16  g_eWih1[(size_t)G4*K3H];
__device__ bf16  g_eWhh1[(size_t)G4*K3H];
__device__ bf16  g_dWhh0[(size_t)G4*K3H];
__device__ bf16  g_dWih1[(size_t)G4*K3H];
__device__ bf16  g_dWhh1[(size_t)G4*K3H];
__device__ bf16  g_Wfold[(size_t)G4*K3H];
__device__ bf16  g_fcW[(size_t)NCP*K3H];
__device__ bf16  g_fcwt[(size_t)H*K3E];     // fcW^T W-style (Wfold operand)
__device__ bf16  g_dwA[(size_t)G4*K3E];     // dWih0 A-style (Wfold operand)
__device__ bf16  g_x3[(size_t)TB*K3E];      // A-style [hi|hi|lo]
__device__ bf16  g_ys3[(size_t)TB*K3H];
__device__ bf16  g_h[4*(size_t)Bn*K3H];     // h0a,h0b,h1a,h1b
__device__ bf16  g_i03[(size_t)Bn*K3E];
__device__ float g_pre[(size_t)TB*G4];
__device__ float g_c[2*Bn*H];
__device__ float g_bias[5*G4 + NCP];

// ---------------- helpers -------------------------------------------------------
__device__ __forceinline__ u32 s2u(const void* p) {
    u32 a; asm("{ .reg .u64 t; cvta.to.shared.u64 t, %1; cvt.u32.u64 %0, t; }" : "=r"(a) : "l"(p)); return a;
}
#define SWZ(o) ((o) ^ (((o) >> 3) & 0x70))
__device__ __forceinline__ float sigmf(float x) { return 1.f / (1.f + __expf(-x)); }
__device__ __forceinline__ void split2(float x, bf16& h, bf16& l) {
    h = __float2bfloat16(x);
    l = __float2bfloat16(x - __bfloat162float(h));
}
__device__ __forceinline__ void ldm4(u32& r0, u32& r1, u32& r2, u32& r3, u32 a) {
    asm volatile("ldmatrix.sync.aligned.m8n8.x4.shared.b16 {%0,%1,%2,%3}, [%4];"
                 : "=r"(r0), "=r"(r1), "=r"(r2), "=r"(r3) : "r"(a));
}
__device__ __forceinline__ void mma16816(float* c, u32 a0, u32 a1, u32 a2, u32 a3, u32 b0, u32 b1) {
    asm volatile(
        "mma.sync.aligned.m16n8k16.row.col.f32.bf16.bf16.f32 "
        "{%0,%1,%2,%3}, {%4,%5,%6,%7}, {%8,%9}, {%0,%1,%2,%3};"
        : "+f"(c[0]), "+f"(c[1]), "+f"(c[2]), "+f"(c[3])
        : "r"(a0), "r"(a1), "r"(a2), "r"(a3), "r"(b0), "r"(b1));
}

// ---------------- HMMA GEMM: D[m,n] = sum_k' A[m,k']*W[n,k'] (dual-A optional) ---
// CTA tile M=128 x N=64, K chunk = 64 elems (128B SW128 rows). 256 threads.
// EPI=0: Cout[row*ldc+col]=acc   EPI=1: fused LSTM   EPI=2: fc scatter +bias
template<int EPI>
__global__ __launch_bounds__(256)
void hgemm(const bf16* __restrict__ A1, int lda1,
           const bf16* __restrict__ W1, int ldw1, int nc1,
           const bf16* __restrict__ A2, int lda2,
           const bf16* __restrict__ W2, int ldw2, int nc2,
           const float* __restrict__ bias, const float* __restrict__ pre,
           float* __restrict__ cst, bf16* __restrict__ hout,
           bf16* __restrict__ ysout, float* __restrict__ Cout, int ldc)
{
    __shared__ bf16 As[2][128*64];
    __shared__ bf16 Ws[2][64*64];

    const int tid = threadIdx.x;
    const int warp = tid >> 5, lane = tid & 31;
    const int wm = warp & 3, wn = warp >> 2;
    const int bm = blockIdx.y * 128, bn = blockIdx.x * 64;

    // loader indices
    const int la_row = tid >> 1;            // A: 128 rows, 2 thr/row
    const int la_kb  = (tid & 1) * 64;      // byte offset within 128B row
    const int lw_row = tid >> 2;            // W: 64 rows, 4 thr/row
    const int lw_kb  = (tid & 3) * 32;

    // ldmatrix indices
    const int a_r  = wm * 32 + (lane & 15);
    const int a_kb = (lane >> 4) * 16;
    const int b_r  = wn * 32 + ((lane >> 4) << 3) + (lane & 7);
    const int b_kb = ((lane >> 3) & 1) * 16;

    const u32 sA[2] = { s2u(As[0]), s2u(As[1]) };
    const u32 sW[2] = { s2u(Ws[0]), s2u(Ws[1]) };

    float acc[2][4][4];
#pragma unroll
    for (int m = 0; m < 2; ++m)
#pragma unroll
        for (int n = 0; n < 4; ++n)
#pragma unroll
            for (int q = 0; q < 4; ++q) acc[m][n][q] = 0.f;

    const int tot = nc1 + nc2;

#define SRCSEL(i, Ag, lda, Wg, ldw, k0)                                    \
    const bf16 *Ag, *Wg; int lda, ldw, k0;                                 \
    if ((i) < nc1) { Ag = A1; Wg = W1; lda = lda1; ldw = ldw1; k0 = (i) * 64; } \
    else           { Ag = A2; Wg = W2; lda = lda2; ldw = ldw2; k0 = ((i) - nc1) * 64; }

    // prologue: chunk 0 -> buf 0
    {
        SRCSEL(0, Ag, lda, Wg, ldw, k0)
        const bf16* ap = Ag + (size_t)(bm + la_row) * lda + k0 + la_kb / 2;
#pragma unroll
        for (int j = 0; j < 4; ++j)
            *(uint4*)((char*)As[0] + SWZ(la_row * 128 + la_kb + j * 16)) = *(const uint4*)(ap + j * 8);
        const bf16* wp = Wg + (size_t)(bn + lw_row) * ldw + k0 + lw_kb / 2;
#pragma unroll
        for (int j = 0; j < 2; ++j)
            *(uint4*)((char*)Ws[0] + SWZ(lw_row * 128 + lw_kb + j * 16)) = *(const uint4*)(wp + j * 8);
    }
    __syncthreads();

    int buf = 0;
    uint4 pa[4], pw[2];
    for (int i = 0; i < tot; ++i) {
        const bool more = (i + 1 < tot);
        if (more) {
            SRCSEL(i + 1, Ag, lda, Wg, ldw, k0)
            const bf16* ap = Ag + (size_t)(bm + la_row) * lda + k0 + la_kb / 2;
#pragma unroll
            for (int j = 0; j < 4; ++j) pa[j] = *(const uint4*)(ap + j * 8);
            const bf16* wp = Wg + (size_t)(bn + lw_row) * ldw + k0 + lw_kb / 2;
#pragma unroll
            for (int j = 0; j < 2; ++j) pw[j] = *(const uint4*)(wp + j * 8);
        }

#pragma unroll
        for (int kk = 0; kk < 4; ++kk) {
            const int kb = kk * 32;
            u32 a0[4], a1[4], bb0[4], bb1[4];
            ldm4(a0[0], a0[1], a0[2], a0[3], sA[buf] + SWZ(a_r * 128 + kb + a_kb));
            ldm4(a1[0], a1[1], a1[2], a1[3], sA[buf] + SWZ((a_r + 16) * 128 + kb + a_kb));
            ldm4(bb0[0], bb0[1], bb0[2], bb0[3], sW[buf] + SWZ(b_r * 128 + kb + b_kb));
            ldm4(bb1[0], bb1[1], bb1[2], bb1[3], sW[buf] + SWZ((b_r + 16) * 128 + kb + b_kb));
            mma16816(acc[0][0], a0[0], a0[1], a0[2], a0[3], bb0[0], bb0[1]);
            mma16816(acc[0][1], a0[0], a0[1], a0[2], a0[3], bb0[2], bb0[3]);
            mma16816(acc[0][2], a0[0], a0[1], a0[2], a0[3], bb1[0], bb1[1]);
            mma16816(acc[0][3], a0[0], a0[1], a0[2], a0[3], bb1[2], bb1[3]);
            mma16816(acc[1][0], a1[0], a1[1], a1[2], a1[3], bb0[0], bb0[1]);
            mma16816(acc[1][1], a1[0], a1[1], a1[2], a1[3], bb0[2], bb0[3]);
            mma16816(acc[1][2], a1[0], a1[1], a1[2], a1[3], bb1[0], bb1[1]);
            mma16816(acc[1][3], a1[0], a1[1], a1[2], a1[3], bb1[2], bb1[3]);
        }

        if (more) {
            const int nb = buf ^ 1;
#pragma unroll
            for (int j = 0; j < 4; ++j)
                *(uint4*)((char*)As[nb] + SWZ(la_row * 128 + la_kb + j * 16)) = pa[j];
#pragma unroll
            for (int j = 0; j < 2; ++j)
                *(uint4*)((char*)Ws[nb] + SWZ(lw_row * 128 + lw_kb + j * 16)) = pw[j];
            __syncthreads();
            buf = nb;
        }
    }

    // ---------------- epilogues ----------------
    const int rbase = bm + wm * 32 + (lane >> 2);

    if (EPI == 0) {
#pragma unroll
        for (int mt = 0; mt < 2; ++mt) {
#pragma unroll
            for (int nt = 0; nt < 4; ++nt) {
                const int col = bn + wn * 32 + nt * 8 + 2 * (lane & 3);
                const int r1 = rbase + mt * 16, r2 = r1 + 8;
                *(float2*)&Cout[(size_t)r1 * ldc + col] = make_float2(acc[mt][nt][0], acc[mt][nt][1]);
                *(float2*)&Cout[(size_t)r2 * ldc + col] = make_float2(acc[mt][nt][2], acc[mt][nt][3]);
            }
        }
    } else if (EPI == 1) {
#pragma unroll
        for (int mt = 0; mt < 2; ++mt) {
#pragma unroll
            for (int nt = 0; nt < 4; ++nt) {
                float i1 = acc[mt][nt][0], f1 = acc[mt][nt][1];
                float i2 = acc[mt][nt][2], f2 = acc[mt][nt][3];
                const float g1 = __shfl_xor_sync(0xffffffffu, i1, 1);
                const float o1 = __shfl_xor_sync(0xffffffffu, f1, 1);
                const float g2 = __shfl_xor_sync(0xffffffffu, i2, 1);
                const float o2 = __shfl_xor_sync(0xffffffffu, f2, 1);
                if ((lane & 1) == 0) {
                    const int col = bn + wn * 32 + nt * 8 + 2 * (lane & 3);   // mult of 4
                    const int jh = col >> 2;
                    const float4 b4 = *(const float4*)&bias[col];
                    const int r1 = rbase + mt * 16, r2 = r1 + 8;
                    float gi1 = i1 + b4.x, gf1 = f1 + b4.y, gg1 = g1 + b4.z, go1 = o1 + b4.w;
                    float gi2 = i2 + b4.x, gf2 = f2 + b4.y, gg2 = g2 + b4.z, go2 = o2 + b4.w;
                    if (pre) {
                        const float4 p1 = *(const float4*)&pre[(size_t)r1 * G4 + col];
                        const float4 p2 = *(const float4*)&pre[(size_t)r2 * G4 + col];
                        gi1 += p1.x; gf1 += p1.y; gg1 += p1.z; go1 += p1.w;
                        gi2 += p2.x; gf2 += p2.y; gg2 += p2.z; go2 += p2.w;
                    }
                    {
                        const size_t ci = (size_t)r1 * H + jh;
                        const float cv = sigmf(gf1) * cst[ci] + sigmf(gi1) * tanhf(gg1);
                        const float hv = sigmf(go1) * tanhf(cv);
                        cst[ci] = cv;
                        bf16 hh, hl; split2(hv, hh, hl);
                        bf16* hr = hout + (size_t)r1 * K3H;
                        hr[jh] = hh; hr[H + jh] = hh; hr[2 * H + jh] = hl;
                        if (ysout) { bf16* yr = ysout + (size_t)r1 * K3H; yr[jh] = hh; yr[H + jh] = hh; yr[2 * H + jh] = hl; }
                    }
                    {
                        const size_t ci = (size_t)r2 * H + jh;
                        const float cv = sigmf(gf2) * cst[ci] + sigmf(gi2) * tanhf(gg2);
                        const float hv = sigmf(go2) * tanhf(cv);
                        cst[ci] = cv;
                        bf16 hh, hl; split2(hv, hh, hl);
                        bf16* hr = hout + (size_t)r2 * K3H;
                        hr[jh] = hh; hr[H + jh] = hh; hr[2 * H + jh] = hl;
                        if (ysout) { bf16* yr = ysout + (size_t)r2 * K3H; yr[jh] = hh; yr[H + jh] = hh; yr[2 * H + jh] = hl; }
                    }
                }
            }
        }
    } else { // EPI == 2
#pragma unroll
        for (int mt = 0; mt < 2; ++mt) {
#pragma unroll
            for (int nt = 0; nt < 4; ++nt) {
                const int col = bn + wn * 32 + nt * 8 + 2 * (lane & 3);
                const int r1 = rbase + mt * 16, r2 = r1 + 8;
                {
                    const int bb = r1 & (Bn - 1), tt = r1 >> 9;
                    float* o = Cout + (size_t)bb * (Pn * CCn) + (size_t)tt * CCn;
                    if (col < CCn)     o[col]     = acc[mt][nt][0] + bias[col];
                    if (col + 1 < CCn) o[col + 1] = acc[mt][nt][1] + bias[col + 1];
                }
                {
                    const int bb = r2 & (Bn - 1), tt = r2 >> 9;
                    float* o = Cout + (size_t)bb * (Pn * CCn) + (size_t)tt * CCn;
                    if (col < CCn)     o[col]     = acc[mt][nt][2] + bias[col];
                    if (col + 1 < CCn) o[col + 1] = acc[mt][nt][3] + bias[col + 1];
                }
            }
        }
    }
#undef SRCSEL
}

// ---------------- setup kernels ---------------------------------------------------
// W-style split3 of interleaved weight rows: dst[np][3Kp] = [hi|lo|hi]
__global__ void k_w3(const float* __restrict__ src, bf16* __restrict__ dst, int K, int Kp)
{
    size_t idx = (size_t)blockIdx.x * blockDim.x + threadIdx.x;
    if (idx >= (size_t)G4 * Kp) return;
    int np = (int)(idx / Kp), k = (int)(idx % Kp);
    int j = np >> 2, g = np & 3;
    float v = (k < K) ? src[((size_t)(g * H + j)) * K + k] : 0.f;
    bf16 h, l; split2(v, h, l);
    bf16* d = dst + (size_t)np * 3 * Kp;
    d[k] = h; d[Kp + k] = l; d[2 * Kp + k] = h;
}
// A-style split3 of interleaved rows: [hi|hi|lo]
__global__ void k_a3w(const float* __restrict__ src, bf16* __restrict__ dst, int K, int Kp)
{
    size_t idx = (size_t)blockIdx.x * blockDim.x + threadIdx.x;
    if (idx >= (size_t)G4 * Kp) return;
    int np = (int)(idx / Kp), k = (int)(idx % Kp);
    int j = np >> 2, g = np & 3;
    float v = (k < K) ? src[((size_t)(g * H + j)) * K + k] : 0.f;
    bf16 h, l; split2(v, h, l);
    bf16* d = dst + (size_t)np * 3 * Kp;
    d[k] = h; d[Kp + k] = h; d[2 * Kp + k] = l;
}
__global__ void k_fcwt3(const float* __restrict__ fcW, bf16* __restrict__ dst)
{
    int idx = blockIdx.x * blockDim.x + threadIdx.x;
    if (idx >= H * EPB) return;
    int hrow = idx / EPB, c = idx % EPB;
    float v = (c < CCn) ? fcW[(size_t)c * H + hrow] : 0.f;
    bf16 h, l; split2(v, h, l);
    bf16* d = dst + (size_t)hrow * K3E;
    d[c] = h; d[EPB + c] = l; d[2 * EPB + c] = h;
}
__global__ void k_fcw3(const float* __restrict__ fcW, bf16* __restrict__ dst)
{
    int idx = blockIdx.x * blockDim.x + threadIdx.x;
    if (idx >= NCP * H) return;
    int n = idx / H, hcol = idx % H;
    float v = (n < CCn) ? fcW[(size_t)n * H + hcol] : 0.f;
    bf16 h, l; split2(v, h, l);
    bf16* d = dst + (size_t)n * K3H;
    d[hcol] = h; d[H + hcol] = l; d[2 * H + hcol] = h;
}
__global__ void k_split3w(const float* __restrict__ src, bf16* __restrict__ dst)  // Wfold
{
    size_t idx = (size_t)blockIdx.x * blockDim.x + threadIdx.x;
    if (idx >= (size_t)G4 * H) return;
    int np = (int)(idx / H), k = (int)(idx % H);
    bf16 h, l; split2(src[idx], h, l);
    bf16* d = dst + (size_t)np * K3H;
    d[k] = h; d[H + k] = l; d[2 * H + k] = h;
}
__global__ void k_x3(const float* __restrict__ x, bf16* __restrict__ dst)
{
    size_t idx = (size_t)blockIdx.x * blockDim.x + threadIdx.x;
    if (idx >= (size_t)TB * EPB) return;
    int e = (int)(idx % EPB);
    int b = (int)((idx / EPB) % Bn);
    int t = (int)(idx / ((size_t)EPB * Bn));
    float v = (e < E) ? x[(size_t)b * Tn * E + (size_t)t * E + e] : 0.f;
    bf16 h, l; split2(v, h, l);
    bf16* d = dst + ((size_t)t * Bn + b) * K3E;
    d[e] = h; d[EPB + e] = h; d[2 * EPB + e] = l;
}
__global__ void k_i03(const float* __restrict__ x, bf16* __restrict__ dst)
{
    int i = blockIdx.x * blockDim.x + threadIdx.x;
    if (i >= Bn * EPB) return;
    int b = i / EPB, e = i % EPB;
    float v = (e < E) ? x[(size_t)b * Tn * E + (size_t)(Tn - 1) * E + e] : 0.f;
    bf16 h, l; split2(v, h, l);
    bf16* d = dst + (size_t)b * K3E;
    d[e] = h; d[EPB + e] = h; d[2 * EPB + e] = l;
}
__global__ void k_bias(const float* __restrict__ a, const float* __restrict__ b, float* __restrict__ d)
{
    int n = blockIdx.x * blockDim.x + threadIdx.x;
    if (n >= G4) return;
    int j = n >> 2, g = n & 3;
    d[n] = a[g * H + j] + b[g * H + j];
}
__global__ void k_foldbias(const float* __restrict__ dWih0, const float* __restrict__ fcb,
                           const float* __restrict__ dB0, float* __restrict__ out)
{
    int n = blockIdx.x * blockDim.x + threadIdx.x;
    if (n >= G4) return;
    int j = n >> 2, g = n & 3;
    float s = dB0[n];
    const float* row = dWih0 + (size_t)(g * H + j) * E;
    for (int c = 0; c < CCn; ++c) s += row[c] * fcb[c];
    out[n] = s;
}
__global__ void k_fcb(const float* __restrict__ fcb, float* __restrict__ d)
{
    int n = blockIdx.x * blockDim.x + threadIdx.x;
    if (n >= NCP) return;
    d[n] = (n < CCn) ? fcb[n] : 0.f;
}
__global__ void k_zf(float* p, int n) { int i = blockIdx.x * blockDim.x + threadIdx.x; if (i < n) p[i] = 0.f; }
__global__ void k_zb(bf16* p, size_t n) { size_t i = (size_t)blockIdx.x * blockDim.x + threadIdx.x; if (i < n) ((unsigned short*)p)[i] = 0; }

// ---------------- entry ----------------------------------------------------------
extern "C" void kernel_launch(void* const* d_in, const int* in_sizes, int n_in,
                              void* d_out, int out_size)
{
    const float* x_enc  = (const float*)d_in[0];
    const float* e_Wih0 = (const float*)d_in[4],  *e_Whh0 = (const float*)d_in[5];
    const float* e_bih0 = (const float*)d_in[6],  *e_bhh0 = (const float*)d_in[7];
    const float* e_Wih1 = (const float*)d_in[8],  *e_Whh1 = (const float*)d_in[9];
    const float* e_bih1 = (const float*)d_in[10], *e_bhh1 = (const float*)d_in[11];
    const float* d_Wih0 = (const float*)d_in[12], *d_Whh0 = (const float*)d_in[13];
    const float* d_bih0 = (const float*)d_in[14], *d_bhh0 = (const float*)d_in[15];
    const float* d_Wih1 = (const float*)d_in[16], *d_Whh1 = (const float*)d_in[17];
    const float* d_bih1 = (const float*)d_in[18], *d_bhh1 = (const float*)d_in[19];
    const float* fc_W   = (const float*)d_in[20], *fc_b   = (const float*)d_in[21];
    float* out = (float*)d_out;

    bf16 *eWih0, *dWih0, *eWhh0, *eWih1, *eWhh1, *dWhh0, *dWih1, *dWhh1;
    bf16 *Wfold, *fcW3, *fcwt, *dwA, *x3, *ys3, *hB, *i03;
    float *pre, *cbuf, *bias;
    cudaGetSymbolAddress((void**)&eWih0, g_eWih0); cudaGetSymbolAddress((void**)&dWih0, g_dWih0);
    cudaGetSymbolAddress((void**)&eWhh0, g_eWhh0); cudaGetSymbolAddress((void**)&eWih1, g_eWih1);
    cudaGetSymbolAddress((void**)&eWhh1, g_eWhh1); cudaGetSymbolAddress((void**)&dWhh0, g_dWhh0);
    cudaGetSymbolAddress((void**)&dWih1, g_dWih1); cudaGetSymbolAddress((void**)&dWhh1, g_dWhh1);
    cudaGetSymbolAddress((void**)&Wfold, g_Wfold); cudaGetSymbolAddress((void**)&fcW3,  g_fcW);
    cudaGetSymbolAddress((void**)&fcwt,  g_fcwt);  cudaGetSymbolAddress((void**)&dwA,   g_dwA);
    cudaGetSymbolAddress((void**)&x3,    g_x3);    cudaGetSymbolAddress((void**)&ys3,   g_ys3);
    cudaGetSymbolAddress((void**)&hB,    g_h);     cudaGetSymbolAddress((void**)&i03,   g_i03);
    cudaGetSymbolAddress((void**)&pre,   g_pre);   cudaGetSymbolAddress((void**)&cbuf,  g_c);
    cudaGetSymbolAddress((void**)&bias,  g_bias);

    float* eB0  = bias;          float* eB1 = bias + G4;
    float* dB0  = bias + 2 * G4; float* dB1 = bias + 3 * G4;
    float* dB0f = bias + 4 * G4; float* fcb = bias + 5 * G4;
    const size_t HP = (size_t)Bn * K3H;
    bf16* h0[2] = { hB,          hB + HP };
    bf16* h1[2] = { hB + 2 * HP, hB + 3 * HP };
    float* c0 = cbuf; float* c1 = cbuf + (size_t)Bn * H;
    const int thr = 256;
    const size_t BHK = (size_t)Bn * K3H;

    // ---- setup ----
    {
        size_t nE = (size_t)G4 * EPB, nH = (size_t)G4 * H;
        k_w3<<<(unsigned)((nE + thr - 1) / thr), thr>>>(e_Wih0, eWih0, E, EPB);
        k_w3<<<(unsigned)((nE + thr - 1) / thr), thr>>>(d_Wih0, dWih0, E, EPB);
        k_w3<<<(unsigned)((nH + thr - 1) / thr), thr>>>(e_Whh0, eWhh0, H, H);
        k_w3<<<(unsigned)((nH + thr - 1) / thr), thr>>>(e_Wih1, eWih1, H, H);
        k_w3<<<(unsigned)((nH + thr - 1) / thr), thr>>>(e_Whh1, eWhh1, H, H);
        k_w3<<<(unsigned)((nH + thr - 1) / thr), thr>>>(d_Whh0, dWhh0, H, H);
        k_w3<<<(unsigned)((nH + thr - 1) / thr), thr>>>(d_Wih1, dWih1, H, H);
        k_w3<<<(unsigned)((nH + thr - 1) / thr), thr>>>(d_Whh1, dWhh1, H, H);
        k_a3w<<<(unsigned)((nE + thr - 1) / thr), thr>>>(d_Wih0, dwA, E, EPB);
        k_fcwt3<<<(H * EPB + thr - 1) / thr, thr>>>(fc_W, fcwt);
        k_fcw3<<<(NCP * H + thr - 1) / thr, thr>>>(fc_W, fcW3);
        k_bias<<<(G4 + thr - 1) / thr, thr>>>(e_bih0, e_bhh0, eB0);
        k_bias<<<(G4 + thr - 1) / thr, thr>>>(e_bih1, e_bhh1, eB1);
        k_bias<<<(G4 + thr - 1) / thr, thr>>>(d_bih0, d_bhh0, dB0);
        k_bias<<<(G4 + thr - 1) / thr, thr>>>(d_bih1, d_bhh1, dB1);
        k_foldbias<<<(G4 + thr - 1) / thr, thr>>>(d_Wih0, fc_b, dB0, dB0f);
        k_fcb<<<(NCP + thr - 1) / thr, thr>>>(fc_b, fcb);
    }
    // Wfold = dWih0' @ fcW^T (fp32) then split3 W-style
    {
        dim3 g(H / 64, G4 / 128);
        hgemm<0><<<g, 256>>>(dwA, K3E, fcwt, K3E, K3E / 64,
                             (const bf16*)0, 0, (const bf16*)0, 0, 0,
                             (const float*)0, (const float*)0,
                             (float*)0, (bf16*)0, (bf16*)0, pre, H);
        size_t n = (size_t)G4 * H;
        k_split3w<<<(unsigned)((n + thr - 1) / thr), thr>>>(pre, Wfold);
    }
    // ---- states + inputs ----
    k_zf<<<(2 * Bn * H + thr - 1) / thr, thr>>>(cbuf, 2 * Bn * H);
    k_zb<<<(unsigned)((4 * BHK + thr - 1) / thr), thr>>>(hB, 4 * BHK);
    {
        size_t n = (size_t)TB * EPB;
        k_x3<<<(unsigned)((n + thr - 1) / thr), thr>>>(x_enc, x3);
    }
    k_i03<<<(Bn * EPB + thr - 1) / thr, thr>>>(x_enc, i03);

    // ---- encoder L0 ----
    {
        dim3 g(G4 / 64, TB / 128);
        hgemm<0><<<g, 256>>>(x3, K3E, eWih0, K3E, K3E / 64,
                             (const bf16*)0, 0, (const bf16*)0, 0, 0,
                             (const float*)0, (const float*)0,
                             (float*)0, (bf16*)0, (bf16*)0, pre, G4);
    }
    dim3 gs(G4 / 64, Bn / 128);
    int p0 = 0, p1 = 0;
    for (int t = 0; t < Tn; ++t) {
        hgemm<1><<<gs, 256>>>(h0[p0], K3H, eWhh0, K3H, K3H / 64,
                              (const bf16*)0, 0, (const bf16*)0, 0, 0,
                              eB0, pre + (size_t)t * Bn * G4,
                              c0, h0[p0 ^ 1], ys3 + (size_t)t * BHK, (float*)0, 0);
        p0 ^= 1;
    }
    // ---- encoder L1 ----
    {
        dim3 g(G4 / 64, TB / 128);
        hgemm<0><<<g, 256>>>(ys3, K3H, eWih1, K3H, K3H / 64,
                             (const bf16*)0, 0, (const bf16*)0, 0, 0,
                             (const float*)0, (const float*)0,
                             (float*)0, (bf16*)0, (bf16*)0, pre, G4);
    }
    for (int t = 0; t < Tn; ++t) {
        hgemm<1><<<gs, 256>>>(h1[p1], K3H, eWhh1, K3H, K3H / 64,
                              (const bf16*)0, 0, (const bf16*)0, 0, 0,
                              eB1, pre + (size_t)t * Bn * G4,
                              c1, h1[p1 ^ 1], (bf16*)0, (float*)0, 0);
        p1 ^= 1;
    }
    // ---- decoder ----
    for (int t = 0; t < Pn; ++t) {
        if (t == 0) {
            hgemm<1><<<gs, 256>>>(i03, K3E, dWih0, K3E, K3E / 64,
                                  h0[p0], K3H, dWhh0, K3H, K3H / 64,
                                  dB0, (const float*)0,
                                  c0, h0[p0 ^ 1], (bf16*)0, (float*)0, 0);
        } else {
            hgemm<1><<<gs, 256>>>(h1[p1], K3H, Wfold, K3H, K3H / 64,
                                  h0[p0], K3H, dWhh0, K3H, K3H / 64,
                                  dB0f, (const float*)0,
                                  c0, h0[p0 ^ 1], (bf16*)0, (float*)0, 0);
        }
        p0 ^= 1;
        hgemm<1><<<gs, 256>>>(h0[p0], K3H, dWih1, K3H, K3H / 64,
                              h1[p1], K3H, dWhh1, K3H, K3H / 64,
                              dB1, (const float*)0,
                              c1, h1[p1 ^ 1], ys3 + (size_t)t * BHK, (float*)0, 0);
        p1 ^= 1;
    }
    // ---- batched final fc ----
    {
        dim3 g(NCP / 64, TB / 128);
        hgemm<2><<<g, 256>>>(ys3, K3H, fcW3, K3H, K3H / 64,
                             (const bf16*)0, 0, (const bf16*)0, 0, 0,
                             fcb, (const float*)0,
                             (float*)0, (bf16*)0, (bf16*)0, out, 0);
    }
}

// round 8
// speedup vs baseline: 2.2281x; 1.1034x over previous
#include <cuda_runtime.h>
#include <cuda_bf16.h>
#include <math.h>

#define H   512
#define E   321
#define CCn 321
#define Tn  96
#define Pn  96
#define Bn  512
#define G4  2048
#define EPB 384
#define NCP 384
#define TB  (Tn*Bn)
#define K3E (3*EPB)        // 1152
#define K3H (3*H)          // 1536
#define NCTAS 128

typedef __nv_bfloat16 bf16;
typedef unsigned int u32;

// ---------------- device globals ------------------------------------------------
__device__ bf16  g_eWih0[(size_t)G4*K3E];
__device__ bf16  g_dWih0[(size_t)G4*K3E];
__device__ bf16  g_eWhh0[(size_t)G4*K3H];
__device__ bf16  g_eWih1[(size_t)G4*K3H];
__device__ bf16  g_eWhh1[(size_t)G4*K3H];
__device__ bf16  g_dWhh0[(size_t)G4*K3H];
__device__ bf16  g_dWih1[(size_t)G4*K3H];
__device__ bf16  g_dWhh1[(size_t)G4*K3H];
__device__ bf16  g_Wfold[(size_t)G4*K3H];
__device__ bf16  g_fcW[(size_t)NCP*K3H];
__device__ bf16  g_fcwt[(size_t)H*K3E];
__device__ bf16  g_dwA[(size_t)G4*K3E];
__device__ bf16  g_x3[(size_t)TB*K3E];
__device__ bf16  g_ys3[(size_t)TB*K3H];
__device__ bf16  g_h[4*(size_t)Bn*K3H];
__device__ bf16  g_i03[(size_t)Bn*K3E];
__device__ float g_pre[(size_t)TB*G4];
__device__ float g_c[2*Bn*H];
__device__ float g_bias[5*G4 + NCP];
__device__ unsigned g_bar[8];

// ---------------- helpers -------------------------------------------------------
__device__ __forceinline__ u32 s2u(const void* p) {
    u32 a; asm("{ .reg .u64 t; cvta.to.shared.u64 t, %1; cvt.u32.u64 %0, t; }" : "=r"(a) : "l"(p)); return a;
}
#define SWZ(o) ((o) ^ (((o) >> 3) & 0x70))
__device__ __forceinline__ float sigmf(float x) { return 1.f / (1.f + __expf(-x)); }
__device__ __forceinline__ void split2(float x, bf16& h, bf16& l) {
    h = __float2bfloat16(x);
    l = __float2bfloat16(x - __bfloat162float(h));
}
__device__ __forceinline__ void ldm4(u32& r0, u32& r1, u32& r2, u32& r3, u32 a) {
    asm volatile("ldmatrix.sync.aligned.m8n8.x4.shared.b16 {%0,%1,%2,%3}, [%4];"
                 : "=r"(r0), "=r"(r1), "=r"(r2), "=r"(r3) : "r"(a));
}
__device__ __forceinline__ void mma16816(float* c, u32 a0, u32 a1, u32 a2, u32 a3, u32 b0, u32 b1) {
    asm volatile(
        "mma.sync.aligned.m16n8k16.row.col.f32.bf16.bf16.f32 "
        "{%0,%1,%2,%3}, {%4,%5,%6,%7}, {%8,%9}, {%0,%1,%2,%3};"
        : "+f"(c[0]), "+f"(c[1]), "+f"(c[2]), "+f"(c[3])
        : "r"(a0), "r"(a1), "r"(a2), "r"(a3), "r"(b0), "r"(b1));
}

// ---------------- grid barrier (all CTAs co-resident: grid=128 <= 148 SMs) ------
__device__ __forceinline__ void gridbar(unsigned* cnt, volatile unsigned* rel, unsigned& phase)
{
    __syncthreads();
    if (threadIdx.x == 0) {
        __threadfence();
        const unsigned target = phase + 1u;
        const unsigned v = atomicAdd(cnt, 1u);
        if (v == target * (unsigned)NCTAS - 1u) {
            __threadfence();
            *rel = target;
        } else {
            while (*rel < target) { __nanosleep(64); }
        }
    }
    __syncthreads();
    __threadfence();
    phase += 1u;
}

// ---------------- shared GEMM body (identical math to round-7 hgemm) ------------
__device__ __forceinline__ void gemm_body(
    char* As0, char* As1, char* Ws0, char* Ws1,
    const bf16* A1, int lda1, const bf16* W1, int ldw1, int nc1,
    const bf16* A2, int lda2, const bf16* W2, int ldw2, int nc2,
    int bm, int bn, float acc[2][4][4])
{
    const int tid = threadIdx.x;
    const int warp = tid >> 5, lane = tid & 31;
    const int wm = warp & 3, wn = warp >> 2;
    const int la_row = tid >> 1, la_kb = (tid & 1) * 64;
    const int lw_row = tid >> 2, lw_kb = (tid & 3) * 32;
    const int a_r = wm * 32 + (lane & 15), a_kb = (lane >> 4) * 16;
    const int b_r = wn * 32 + ((lane >> 4) << 3) + (lane & 7), b_kb = ((lane >> 3) & 1) * 16;
    const u32 sA0 = s2u(As0), sA1v = s2u(As1), sW0 = s2u(Ws0), sW1v = s2u(Ws1);
    const int tot = nc1 + nc2;

    // prologue: chunk 0 -> buf 0
    {
        const bf16 *Ag, *Wg; int lda, ldw;
        if (0 < nc1) { Ag = A1; Wg = W1; lda = lda1; ldw = ldw1; }
        else         { Ag = A2; Wg = W2; lda = lda2; ldw = ldw2; }
        const bf16* ap = Ag + (size_t)(bm + la_row) * lda + la_kb / 2;
#pragma unroll
        for (int j = 0; j < 4; ++j)
            *(uint4*)(As0 + SWZ(la_row * 128 + la_kb + j * 16)) = *(const uint4*)(ap + j * 8);
        const bf16* wp = Wg + (size_t)(bn + lw_row) * ldw + lw_kb / 2;
#pragma unroll
        for (int j = 0; j < 2; ++j)
            *(uint4*)(Ws0 + SWZ(lw_row * 128 + lw_kb + j * 16)) = *(const uint4*)(wp + j * 8);
    }
    __syncthreads();

    int buf = 0;
    uint4 pa[4], pw[2];
    for (int i = 0; i < tot; ++i) {
        const bool more = (i + 1 < tot);
        if (more) {
            const bf16 *Ag, *Wg; int lda, ldw, k0;
            if (i + 1 < nc1) { Ag = A1; Wg = W1; lda = lda1; ldw = ldw1; k0 = (i + 1) * 64; }
            else             { Ag = A2; Wg = W2; lda = lda2; ldw = ldw2; k0 = (i + 1 - nc1) * 64; }
            const bf16* ap = Ag + (size_t)(bm + la_row) * lda + k0 + la_kb / 2;
#pragma unroll
            for (int j = 0; j < 4; ++j) pa[j] = *(const uint4*)(ap + j * 8);
            const bf16* wp = Wg + (size_t)(bn + lw_row) * ldw + k0 + lw_kb / 2;
#pragma unroll
            for (int j = 0; j < 2; ++j) pw[j] = *(const uint4*)(wp + j * 8);
        }
        const u32 sAc = buf ? sA1v : sA0;
        const u32 sWc = buf ? sW1v : sW0;
#pragma unroll
        for (int kk = 0; kk < 4; ++kk) {
            const int kb = kk * 32;
            u32 a0[4], a1[4], bb0[4], bb1[4];
            ldm4(a0[0], a0[1], a0[2], a0[3], sAc + SWZ(a_r * 128 + kb + a_kb));
            ldm4(a1[0], a1[1], a1[2], a1[3], sAc + SWZ((a_r + 16) * 128 + kb + a_kb));
            ldm4(bb0[0], bb0[1], bb0[2], bb0[3], sWc + SWZ(b_r * 128 + kb + b_kb));
            ldm4(bb1[0], bb1[1], bb1[2], bb1[3], sWc + SWZ((b_r + 16) * 128 + kb + b_kb));
            mma16816(acc[0][0], a0[0], a0[1], a0[2], a0[3], bb0[0], bb0[1]);
            mma16816(acc[0][1], a0[0], a0[1], a0[2], a0[3], bb0[2], bb0[3]);
            mma16816(acc[0][2], a0[0], a0[1], a0[2], a0[3], bb1[0], bb1[1]);
            mma16816(acc[0][3], a0[0], a0[1], a0[2], a0[3], bb1[2], bb1[3]);
            mma16816(acc[1][0], a1[0], a1[1], a1[2], a1[3], bb0[0], bb0[1]);
            mma16816(acc[1][1], a1[0], a1[1], a1[2], a1[3], bb0[2], bb0[3]);
            mma16816(acc[1][2], a1[0], a1[1], a1[2], a1[3], bb1[0], bb1[1]);
            mma16816(acc[1][3], a1[0], a1[1], a1[2], a1[3], bb1[2], bb1[3]);
        }
        if (more) {
            char* Asn = buf ? As0 : As1;
            char* Wsn = buf ? Ws0 : Ws1;
#pragma unroll
            for (int j = 0; j < 4; ++j)
                *(uint4*)(Asn + SWZ(la_row * 128 + la_kb + j * 16)) = pa[j];
#pragma unroll
            for (int j = 0; j < 2; ++j)
                *(uint4*)(Wsn + SWZ(lw_row * 128 + lw_kb + j * 16)) = pw[j];
            __syncthreads();
            buf ^= 1;
        }
    }
}

// ---------------- fused LSTM epilogue (identical math to round-7 EPI=1) ---------
__device__ __forceinline__ void lstm_epi(
    float acc[2][4][4], int bm, int bn,
    const float* bias, const float* pre,
    float* cst, bf16* hout, bf16* ysout)
{
    const int tid = threadIdx.x;
    const int warp = tid >> 5, lane = tid & 31;
    const int wm = warp & 3, wn = warp >> 2;
    const int rbase = bm + wm * 32 + (lane >> 2);
#pragma unroll
    for (int mt = 0; mt < 2; ++mt) {
#pragma unroll
        for (int nt = 0; nt < 4; ++nt) {
            float i1 = acc[mt][nt][0], f1 = acc[mt][nt][1];
            float i2 = acc[mt][nt][2], f2 = acc[mt][nt][3];
            const float gg1 = __shfl_xor_sync(0xffffffffu, i1, 1);
            const float oo1 = __shfl_xor_sync(0xffffffffu, f1, 1);
            const float gg2 = __shfl_xor_sync(0xffffffffu, i2, 1);
            const float oo2 = __shfl_xor_sync(0xffffffffu, f2, 1);
            if ((lane & 1) == 0) {
                const int col = bn + wn * 32 + nt * 8 + 2 * (lane & 3);
                const int jh = col >> 2;
                const float4 b4 = *(const float4*)&bias[col];
                const int r1 = rbase + mt * 16, r2 = r1 + 8;
                float gi1 = i1 + b4.x, gf1 = f1 + b4.y, gG1 = gg1 + b4.z, go1 = oo1 + b4.w;
                float gi2 = i2 + b4.x, gf2 = f2 + b4.y, gG2 = gg2 + b4.z, go2 = oo2 + b4.w;
                if (pre) {
                    const float4 p1 = *(const float4*)&pre[(size_t)r1 * G4 + col];
                    const float4 p2 = *(const float4*)&pre[(size_t)r2 * G4 + col];
                    gi1 += p1.x; gf1 += p1.y; gG1 += p1.z; go1 += p1.w;
                    gi2 += p2.x; gf2 += p2.y; gG2 += p2.z; go2 += p2.w;
                }
                {
                    const size_t ci = (size_t)r1 * H + jh;
                    const float cv = sigmf(gf1) * cst[ci] + sigmf(gi1) * tanhf(gG1);
                    const float hv = sigmf(go1) * tanhf(cv);
                    cst[ci] = cv;
                    bf16 hh, hl; split2(hv, hh, hl);
                    bf16* hr = hout + (size_t)r1 * K3H;
                    hr[jh] = hh; hr[H + jh] = hh; hr[2 * H + jh] = hl;
                    if (ysout) { bf16* yr = ysout + (size_t)r1 * K3H; yr[jh] = hh; yr[H + jh] = hh; yr[2 * H + jh] = hl; }
                }
                {
                    const size_t ci = (size_t)r2 * H + jh;
                    const float cv = sigmf(gf2) * cst[ci] + sigmf(gi2) * tanhf(gG2);
                    const float hv = sigmf(go2) * tanhf(cv);
                    cst[ci] = cv;
                    bf16 hh, hl; split2(hv, hh, hl);
                    bf16* hr = hout + (size_t)r2 * K3H;
                    hr[jh] = hh; hr[H + jh] = hh; hr[2 * H + jh] = hl;
                    if (ysout) { bf16* yr = ysout + (size_t)r2 * K3H; yr[jh] = hh; yr[H + jh] = hh; yr[2 * H + jh] = hl; }
                }
            }
        }
    }
}

// ---------------- batched GEMM kernel (EPI=0 plain fp32 out, EPI=2 fc scatter) --
template<int EPI>
__global__ __launch_bounds__(256)
void hgemm(const bf16* __restrict__ A1, int lda1,
           const bf16* __restrict__ W1, int ldw1, int nc1,
           const float* __restrict__ bias,
           float* __restrict__ Cout, int ldc)
{
    __shared__ bf16 As[2][128*64];
    __shared__ bf16 Ws[2][64*64];
    const int bm = blockIdx.y * 128, bn = blockIdx.x * 64;
    float acc[2][4][4];
#pragma unroll
    for (int m = 0; m < 2; ++m)
#pragma unroll
        for (int n = 0; n < 4; ++n)
#pragma unroll
            for (int q = 0; q < 4; ++q) acc[m][n][q] = 0.f;

    gemm_body((char*)As[0], (char*)As[1], (char*)Ws[0], (char*)Ws[1],
              A1, lda1, W1, ldw1, nc1,
              (const bf16*)0, 0, (const bf16*)0, 0, 0, bm, bn, acc);

    const int tid = threadIdx.x;
    const int warp = tid >> 5, lane = tid & 31;
    const int wm = warp & 3, wn = warp >> 2;
    const int rbase = bm + wm * 32 + (lane >> 2);

    if (EPI == 0) {
#pragma unroll
        for (int mt = 0; mt < 2; ++mt) {
#pragma unroll
            for (int nt = 0; nt < 4; ++nt) {
                const int col = bn + wn * 32 + nt * 8 + 2 * (lane & 3);
                const int r1 = rbase + mt * 16, r2 = r1 + 8;
                *(float2*)&Cout[(size_t)r1 * ldc + col] = make_float2(acc[mt][nt][0], acc[mt][nt][1]);
                *(float2*)&Cout[(size_t)r2 * ldc + col] = make_float2(acc[mt][nt][2], acc[mt][nt][3]);
            }
        }
    } else {
#pragma unroll
        for (int mt = 0; mt < 2; ++mt) {
#pragma unroll
            for (int nt = 0; nt < 4; ++nt) {
                const int col = bn + wn * 32 + nt * 8 + 2 * (lane & 3);
                const int r1 = rbase + mt * 16, r2 = r1 + 8;
                {
                    const int bb = r1 & (Bn - 1), tt = r1 >> 9;
                    float* o = Cout + (size_t)bb * (Pn * CCn) + (size_t)tt * CCn;
                    if (col < CCn)     o[col]     = acc[mt][nt][0] + bias[col];
                    if (col + 1 < CCn) o[col + 1] = acc[mt][nt][1] + bias[col + 1];
                }
                {
                    const int bb = r2 & (Bn - 1), tt = r2 >> 9;
                    float* o = Cout + (size_t)bb * (Pn * CCn) + (size_t)tt * CCn;
                    if (col < CCn)     o[col]     = acc[mt][nt][2] + bias[col];
                    if (col + 1 < CCn) o[col + 1] = acc[mt][nt][3] + bias[col + 1];
                }
            }
        }
    }
}

// ---------------- persistent encoder-layer recurrence ---------------------------
__global__ __launch_bounds__(256)
void enc_seq(bf16* hA, bf16* hBp, const bf16* __restrict__ W,
             const float* __restrict__ bias, const float* __restrict__ preBase,
             float* __restrict__ cst, bf16* __restrict__ ysBase, int steps,
             unsigned* barCnt, unsigned* barRel)
{
    __shared__ bf16 As[2][128*64];
    __shared__ bf16 Ws[2][64*64];
    const int bm = blockIdx.y * 128, bn = blockIdx.x * 64;
    bf16* hc = hA; bf16* hn = hBp;
    unsigned phase = 0;
    for (int t = 0; t < steps; ++t) {
        float acc[2][4][4];
#pragma unroll
        for (int m = 0; m < 2; ++m)
#pragma unroll
            for (int n = 0; n < 4; ++n)
#pragma unroll
                for (int q = 0; q < 4; ++q) acc[m][n][q] = 0.f;
        gemm_body((char*)As[0], (char*)As[1], (char*)Ws[0], (char*)Ws[1],
                  hc, K3H, W, K3H, K3H / 64,
                  (const bf16*)0, 0, (const bf16*)0, 0, 0, bm, bn, acc);
        lstm_epi(acc, bm, bn, bias, preBase + (size_t)t * Bn * G4, cst, hn,
                 ysBase ? (ysBase + (size_t)t * Bn * K3H) : (bf16*)0);
        gridbar(barCnt, (volatile unsigned*)barRel, phase);
        bf16* tmp = hc; hc = hn; hn = tmp;
    }
}

// ---------------- persistent decoder recurrence ---------------------------------
__global__ __launch_bounds__(256)
void dec_seq(bf16* h0A, bf16* h0B, bf16* h1A, bf16* h1B,
             const bf16* __restrict__ i03,
             const bf16* __restrict__ dWih0, const bf16* __restrict__ Wfold,
             const bf16* __restrict__ dWhh0, const bf16* __restrict__ dWih1,
             const bf16* __restrict__ dWhh1,
             const float* __restrict__ dB0, const float* __restrict__ dB0f,
             const float* __restrict__ dB1,
             float* __restrict__ c0, float* __restrict__ c1,
             bf16* __restrict__ ysBase, int steps,
             unsigned* barCnt, unsigned* barRel)
{
    __shared__ bf16 As[2][128*64];
    __shared__ bf16 Ws[2][64*64];
    const int bm = blockIdx.y * 128, bn = blockIdx.x * 64;
    bf16 *h0c = h0A, *h0n = h0B, *h1c = h1A, *h1n = h1B;
    unsigned phase = 0;
    for (int t = 0; t < steps; ++t) {
        // ---- cell 0 ----
        {
            float acc[2][4][4];
#pragma unroll
            for (int m = 0; m < 2; ++m)
#pragma unroll
                for (int n = 0; n < 4; ++n)
#pragma unroll
                    for (int q = 0; q < 4; ++q) acc[m][n][q] = 0.f;
            if (t == 0) {
                gemm_body((char*)As[0], (char*)As[1], (char*)Ws[0], (char*)Ws[1],
                          i03, K3E, dWih0, K3E, K3E / 64,
                          h0c, K3H, dWhh0, K3H, K3H / 64, bm, bn, acc);
                lstm_epi(acc, bm, bn, dB0, (const float*)0, c0, h0n, (bf16*)0);
            } else {
                gemm_body((char*)As[0], (char*)As[1], (char*)Ws[0], (char*)Ws[1],
                          h1c, K3H, Wfold, K3H, K3H / 64,
                          h0c, K3H, dWhh0, K3H, K3H / 64, bm, bn, acc);
                lstm_epi(acc, bm, bn, dB0f, (const float*)0, c0, h0n, (bf16*)0);
            }
            gridbar(barCnt, (volatile unsigned*)barRel, phase);
            bf16* tmp = h0c; h0c = h0n; h0n = tmp;
        }
        // ---- cell 1 ----
        {
            float acc[2][4][4];
#pragma unroll
            for (int m = 0; m < 2; ++m)
#pragma unroll
                for (int n = 0; n < 4; ++n)
#pragma unroll
                    for (int q = 0; q < 4; ++q) acc[m][n][q] = 0.f;
            gemm_body((char*)As[0], (char*)As[1], (char*)Ws[0], (char*)Ws[1],
                      h0c, K3H, dWih1, K3H, K3H / 64,
                      h1c, K3H, dWhh1, K3H, K3H / 64, bm, bn, acc);
            lstm_epi(acc, bm, bn, dB1, (const float*)0, c1, h1n,
                     ysBase + (size_t)t * Bn * K3H);
            gridbar(barCnt, (volatile unsigned*)barRel, phase);
            bf16* tmp = h1c; h1c = h1n; h1n = tmp;
        }
    }
}

// ---------------- setup kernels ---------------------------------------------------
__global__ void k_w3(const float* __restrict__ src, bf16* __restrict__ dst, int K, int Kp)
{
    size_t idx = (size_t)blockIdx.x * blockDim.x + threadIdx.x;
    if (idx >= (size_t)G4 * Kp) return;
    int np = (int)(idx / Kp), k = (int)(idx % Kp);
    int j = np >> 2, g = np & 3;
    float v = (k < K) ? src[((size_t)(g * H + j)) * K + k] : 0.f;
    bf16 h, l; split2(v, h, l);
    bf16* d = dst + (size_t)np * 3 * Kp;
    d[k] = h; d[Kp + k] = l; d[2 * Kp + k] = h;
}
__global__ void k_a3w(const float* __restrict__ src, bf16* __restrict__ dst, int K, int Kp)
{
    size_t idx = (size_t)blockIdx.x * blockDim.x + threadIdx.x;
    if (idx >= (size_t)G4 * Kp) return;
    int np = (int)(idx / Kp), k = (int)(idx % Kp);
    int j = np >> 2, g = np & 3;
    float v = (k < K) ? src[((size_t)(g * H + j)) * K + k] : 0.f;
    bf16 h, l; split2(v, h, l);
    bf16* d = dst + (size_t)np * 3 * Kp;
    d[k] = h; d[Kp + k] = h; d[2 * Kp + k] = l;
}
__global__ void k_fcwt3(const float* __restrict__ fcW, bf16* __restrict__ dst)
{
    int idx = blockIdx.x * blockDim.x + threadIdx.x;
    if (idx >= H * EPB) return;
    int hrow = idx / EPB, c = idx % EPB;
    float v = (c < CCn) ? fcW[(size_t)c * H + hrow] : 0.f;
    bf16 h, l; split2(v, h, l);
    bf16* d = dst + (size_t)hrow * K3E;
    d[c] = h; d[EPB + c] = l; d[2 * EPB + c] = h;
}
__global__ void k_fcw3(const float* __restrict__ fcW, bf16* __restrict__ dst)
{
    int idx = blockIdx.x * blockDim.x + threadIdx.x;
    if (idx >= NCP * H) return;
    int n = idx / H, hcol = idx % H;
    float v = (n < CCn) ? fcW[(size_t)n * H + hcol] : 0.f;
    bf16 h, l; split2(v, h, l);
    bf16* d = dst + (size_t)n * K3H;
    d[hcol] = h; d[H + hcol] = l; d[2 * H + hcol] = h;
}
__global__ void k_split3w(const float* __restrict__ src, bf16* __restrict__ dst)
{
    size_t idx = (size_t)blockIdx.x * blockDim.x + threadIdx.x;
    if (idx >= (size_t)G4 * H) return;
    int np = (int)(idx / H), k = (int)(idx % H);
    bf16 h, l; split2(src[idx], h, l);
    bf16* d = dst + (size_t)np * K3H;
    d[k] = h; d[H + k] = l; d[2 * H + k] = h;
}
__global__ void k_x3(const float* __restrict__ x, bf16* __restrict__ dst)
{
    size_t idx = (size_t)blockIdx.x * blockDim.x + threadIdx.x;
    if (idx >= (size_t)TB * EPB) return;
    int e = (int)(idx % EPB);
    int b = (int)((idx / EPB) % Bn);
    int t = (int)(idx / ((size_t)EPB * Bn));
    float v = (e < E) ? x[(size_t)b * Tn * E + (size_t)t * E + e] : 0.f;
    bf16 h, l; split2(v, h, l);
    bf16* d = dst + ((size_t)t * Bn + b) * K3E;
    d[e] = h; d[EPB + e] = h; d[2 * EPB + e] = l;
}
__global__ void k_i03(const float* __restrict__ x, bf16* __restrict__ dst)
{
    int i = blockIdx.x * blockDim.x + threadIdx.x;
    if (i >= Bn * EPB) return;
    int b = i / EPB, e = i % EPB;
    float v = (e < E) ? x[(size_t)b * Tn * E + (size_t)(Tn - 1) * E + e] : 0.f;
    bf16 h, l; split2(v, h, l);
    bf16* d = dst + (size_t)b * K3E;
    d[e] = h; d[EPB + e] = h; d[2 * EPB + e] = l;
}
__global__ void k_bias(const float* __restrict__ a, const float* __restrict__ b, float* __restrict__ d)
{
    int n = blockIdx.x * blockDim.x + threadIdx.x;
    if (n >= G4) return;
    int j = n >> 2, g = n & 3;
    d[n] = a[g * H + j] + b[g * H + j];
}
__global__ void k_foldbias(const float* __restrict__ dWih0, const float* __restrict__ fcb,
                           const float* __restrict__ dB0, float* __restrict__ out)
{
    int n = blockIdx.x * blockDim.x + threadIdx.x;
    if (n >= G4) return;
    int j = n >> 2, g = n & 3;
    float s = dB0[n];
    const float* row = dWih0 + (size_t)(g * H + j) * E;
    for (int c = 0; c < CCn; ++c) s += row[c] * fcb[c];
    out[n] = s;
}
__global__ void k_fcb(const float* __restrict__ fcb, float* __restrict__ d)
{
    int n = blockIdx.x * blockDim.x + threadIdx.x;
    if (n >= NCP) return;
    d[n] = (n < CCn) ? fcb[n] : 0.f;
}
__global__ void k_zf(float* p, int n) { int i = blockIdx.x * blockDim.x + threadIdx.x; if (i < n) p[i] = 0.f; }
__global__ void k_zb(bf16* p, size_t n) { size_t i = (size_t)blockIdx.x * blockDim.x + threadIdx.x; if (i < n) ((unsigned short*)p)[i] = 0; }
__global__ void k_zu(unsigned* p) { if (threadIdx.x < 8) p[threadIdx.x] = 0u; }

// ---------------- entry ----------------------------------------------------------
extern "C" void kernel_launch(void* const* d_in, const int* in_sizes, int n_in,
                              void* d_out, int out_size)
{
    const float* x_enc  = (const float*)d_in[0];
    const float* e_Wih0 = (const float*)d_in[4],  *e_Whh0 = (const float*)d_in[5];
    const float* e_bih0 = (const float*)d_in[6],  *e_bhh0 = (const float*)d_in[7];
    const float* e_Wih1 = (const float*)d_in[8],  *e_Whh1 = (const float*)d_in[9];
    const float* e_bih1 = (const float*)d_in[10], *e_bhh1 = (const float*)d_in[11];
    const float* d_Wih0 = (const float*)d_in[12], *d_Whh0 = (const float*)d_in[13];
    const float* d_bih0 = (const float*)d_in[14], *d_bhh0 = (const float*)d_in[15];
    const float* d_Wih1 = (const float*)d_in[16], *d_Whh1 = (const float*)d_in[17];
    const float* d_bih1 = (const float*)d_in[18], *d_bhh1 = (const float*)d_in[19];
    const float* fc_W   = (const float*)d_in[20], *fc_b   = (const float*)d_in[21];
    float* out = (float*)d_out;

    bf16 *eWih0, *dWih0, *eWhh0, *eWih1, *eWhh1, *dWhh0, *dWih1, *dWhh1;
    bf16 *Wfold, *fcW3, *fcwt, *dwA, *x3, *ys3, *hB, *i03;
    float *pre, *cbuf, *bias;
    unsigned* bar;
    cudaGetSymbolAddress((void**)&eWih0, g_eWih0); cudaGetSymbolAddress((void**)&dWih0, g_dWih0);
    cudaGetSymbolAddress((void**)&eWhh0, g_eWhh0); cudaGetSymbolAddress((void**)&eWih1, g_eWih1);
    cudaGetSymbolAddress((void**)&eWhh1, g_eWhh1); cudaGetSymbolAddress((void**)&dWhh0, g_dWhh0);
    cudaGetSymbolAddress((void**)&dWih1, g_dWih1); cudaGetSymbolAddress((void**)&dWhh1, g_dWhh1);
    cudaGetSymbolAddress((void**)&Wfold, g_Wfold); cudaGetSymbolAddress((void**)&fcW3,  g_fcW);
    cudaGetSymbolAddress((void**)&fcwt,  g_fcwt);  cudaGetSymbolAddress((void**)&dwA,   g_dwA);
    cudaGetSymbolAddress((void**)&x3,    g_x3);    cudaGetSymbolAddress((void**)&ys3,   g_ys3);
    cudaGetSymbolAddress((void**)&hB,    g_h);     cudaGetSymbolAddress((void**)&i03,   g_i03);
    cudaGetSymbolAddress((void**)&pre,   g_pre);   cudaGetSymbolAddress((void**)&cbuf,  g_c);
    cudaGetSymbolAddress((void**)&bias,  g_bias);  cudaGetSymbolAddress((void**)&bar,   g_bar);

    float* eB0  = bias;          float* eB1 = bias + G4;
    float* dB0  = bias + 2 * G4; float* dB1 = bias + 3 * G4;
    float* dB0f = bias + 4 * G4; float* fcb = bias + 5 * G4;
    const size_t HP = (size_t)Bn * K3H;
    bf16* h0A = hB;          bf16* h0B = hB + HP;
    bf16* h1A = hB + 2 * HP; bf16* h1B = hB + 3 * HP;
    float* c0 = cbuf; float* c1 = cbuf + (size_t)Bn * H;
    const int thr = 256;
    const size_t BHK = (size_t)Bn * K3H;

    // ---- setup ----
    {
        size_t nE = (size_t)G4 * EPB, nH = (size_t)G4 * H;
        k_w3<<<(unsigned)((nE + thr - 1) / thr), thr>>>(e_Wih0, eWih0, E, EPB);
        k_w3<<<(unsigned)((nE + thr - 1) / thr), thr>>>(d_Wih0, dWih0, E, EPB);
        k_w3<<<(unsigned)((nH + thr - 1) / thr), thr>>>(e_Whh0, eWhh0, H, H);
        k_w3<<<(unsigned)((nH + thr - 1) / thr), thr>>>(e_Wih1, eWih1, H, H);
        k_w3<<<(unsigned)((nH + thr - 1) / thr), thr>>>(e_Whh1, eWhh1, H, H);
        k_w3<<<(unsigned)((nH + thr - 1) / thr), thr>>>(d_Whh0, dWhh0, H, H);
        k_w3<<<(unsigned)((nH + thr - 1) / thr), thr>>>(d_Wih1, dWih1, H, H);
        k_w3<<<(unsigned)((nH + thr - 1) / thr), thr>>>(d_Whh1, dWhh1, H, H);
        k_a3w<<<(unsigned)((nE + thr - 1) / thr), thr>>>(d_Wih0, dwA, E, EPB);
        k_fcwt3<<<(H * EPB + thr - 1) / thr, thr>>>(fc_W, fcwt);
        k_fcw3<<<(NCP * H + thr - 1) / thr, thr>>>(fc_W, fcW3);
        k_bias<<<(G4 + thr - 1) / thr, thr>>>(e_bih0, e_bhh0, eB0);
        k_bias<<<(G4 + thr - 1) / thr, thr>>>(e_bih1, e_bhh1, eB1);
        k_bias<<<(G4 + thr - 1) / thr, thr>>>(d_bih0, d_bhh0, dB0);
        k_bias<<<(G4 + thr - 1) / thr, thr>>>(d_bih1, d_bhh1, dB1);
        k_foldbias<<<(G4 + thr - 1) / thr, thr>>>(d_Wih0, fc_b, dB0, dB0f);
        k_fcb<<<(NCP + thr - 1) / thr, thr>>>(fc_b, fcb);
        k_zu<<<1, 32>>>(bar);
    }
    // Wfold = dWih0' @ fcW^T (fp32) then split3 W-style
    {
        dim3 g(H / 64, G4 / 128);
        hgemm<0><<<g, 256>>>(dwA, K3E, fcwt, K3E, K3E / 64, (const float*)0, pre, H);
        size_t n = (size_t)G4 * H;
        k_split3w<<<(unsigned)((n + thr - 1) / thr), thr>>>(pre, Wfold);
    }
    // ---- states + inputs ----
    k_zf<<<(2 * Bn * H + thr - 1) / thr, thr>>>(cbuf, 2 * Bn * H);
    k_zb<<<(unsigned)((4 * BHK + thr - 1) / thr), thr>>>(hB, 4 * BHK);
    {
        size_t n = (size_t)TB * EPB;
        k_x3<<<(unsigned)((n + thr - 1) / thr), thr>>>(x_enc, x3);
    }
    k_i03<<<(Bn * EPB + thr - 1) / thr, thr>>>(x_enc, i03);

    // ---- encoder L0: batched input GEMM, then persistent recurrence ----
    {
        dim3 g(G4 / 64, TB / 128);
        hgemm<0><<<g, 256>>>(x3, K3E, eWih0, K3E, K3E / 64, (const float*)0, pre, G4);
    }
    {
        dim3 g(G4 / 64, Bn / 128);  // 32 x 4 = 128 CTAs
        enc_seq<<<g, 256>>>(h0A, h0B, eWhh0, eB0, pre, c0, ys3, Tn, bar + 0, bar + 1);
    }
    // ---- encoder L1 ----
    {
        dim3 g(G4 / 64, TB / 128);
        hgemm<0><<<g, 256>>>(ys3, K3H, eWih1, K3H, K3H / 64, (const float*)0, pre, G4);
    }
    {
        dim3 g(G4 / 64, Bn / 128);
        enc_seq<<<g, 256>>>(h1A, h1B, eWhh1, eB1, pre, c1, (bf16*)0, Tn, bar + 2, bar + 3);
    }
    // ---- decoder (persistent, fc folded) ----
    {
        dim3 g(G4 / 64, Bn / 128);
        dec_seq<<<g, 256>>>(h0A, h0B, h1A, h1B, i03,
                            dWih0, Wfold, dWhh0, dWih1, dWhh1,
                            dB0, dB0f, dB1, c0, c1, ys3, Pn, bar + 4, bar + 5);
    }
    // ---- batched final fc ----
    {
        dim3 g(NCP / 64, TB / 128);
        hgemm<2><<<g, 256>>>(ys3, K3H, fcW3, K3H, K3H / 64, fcb, out, 0);
    }
}